// round 10
// baseline (speedup 1.0000x reference)
#include <cuda_runtime.h>
#include <cuda_fp16.h>
#include <math.h>
#include <stdint.h>

#define QLEN 512
#define MLEN 512
#define KLEN 1024
#define BSZ  16
#define NH   16
#define DH   64
#define DM   1024
#define HID  1024

// ---------------- scratch ----------------
__device__ float  g_V  [(size_t)BSZ*NH*KLEN*DH];          // fp32 V (for transpose)
__device__ __half g_BDh[(size_t)BSZ*NH*QLEN*KLEN];        // BD scores fp16

__device__ __half g_Ah [(size_t)16384*1024];              // cat(mems,w) fp16
__device__ __half g_Wth[(size_t)3072*1024];               // qkv_w^T fp16
__device__ __half g_R2h[(size_t)1024*1024];               // r fp16
__device__ __half g_RWth[(size_t)1024*1024];              // r_w^T fp16
__device__ __half g_OWth[(size_t)1024*1024];              // o_w^T fp16
__device__ __half g_AVh[(size_t)8192*1024];               // attn_vec fp16

__device__ __half g_Qrwh[(size_t)BSZ*NH*QLEN*DH];         // (Q+rw_bias) fp16
__device__ __half g_Qrrh[(size_t)BSZ*NH*QLEN*DH];         // (Q+rr_bias) fp16
__device__ __half g_Khb [(size_t)BSZ*NH*KLEN*DH];         // K fp16
__device__ __half g_Vth [(size_t)BSZ*NH*DH*KLEN];         // V^T fp16
__device__ __half g_Rkh [(size_t)NH*KLEN*DH];             // Rk fp16

// ================= helpers =================
__device__ __forceinline__ uint32_t smem_u32(const void* p) {
    uint32_t a;
    asm("{ .reg .u64 t; cvta.to.shared.u64 t, %1; cvt.u32.u64 %0, t; }" : "=r"(a) : "l"(p));
    return a;
}
__device__ __forceinline__ void ldsm4(uint32_t a[4], uint32_t addr) {
    asm volatile("ldmatrix.sync.aligned.m8n8.x4.shared.b16 {%0,%1,%2,%3}, [%4];"
                 : "=r"(a[0]), "=r"(a[1]), "=r"(a[2]), "=r"(a[3]) : "r"(addr));
}
__device__ __forceinline__ void ldsm2(uint32_t b[2], uint32_t addr) {
    asm volatile("ldmatrix.sync.aligned.m8n8.x2.shared.b16 {%0,%1}, [%2];"
                 : "=r"(b[0]), "=r"(b[1]) : "r"(addr));
}
__device__ __forceinline__ void mma16816(float c[4], const uint32_t a[4], const uint32_t b[2]) {
    asm volatile("mma.sync.aligned.m16n8k16.row.col.f32.f16.f16.f32 "
        "{%0,%1,%2,%3}, {%4,%5,%6,%7}, {%8,%9}, {%0,%1,%2,%3};"
        : "+f"(c[0]), "+f"(c[1]), "+f"(c[2]), "+f"(c[3])
        : "r"(a[0]), "r"(a[1]), "r"(a[2]), "r"(a[3]), "r"(b[0]), "r"(b[1]));
}
__device__ __forceinline__ void cpa16(uint32_t dst, const void* src) {
    asm volatile("cp.async.cg.shared.global [%0], [%1], 16;" :: "r"(dst), "l"(src));
}
#define CPA_COMMIT() asm volatile("cp.async.commit_group;")
#define CPA_WAIT1()  asm volatile("cp.async.wait_group 1;")
#define CPA_WAIT2()  asm volatile("cp.async.wait_group 2;")

__device__ __forceinline__ uint32_t f2h2(float a, float b) {
    __half2 t = __floats2half2_rn(a, b);
    return *reinterpret_cast<uint32_t*>(&t);
}
__device__ __forceinline__ uint32_t sphys(int r, int ch) {   // 128B rows, XOR swizzle
    return (uint32_t)(r * 128 + ((ch ^ (r & 7)) << 4));
}

// ---------------- prep kernels ----------------
__global__ __launch_bounds__(256) void round2_k(
    const float* __restrict__ a, const float* __restrict__ b,
    __half* __restrict__ h, int n4each)
{
    int i = blockIdx.x * 256 + threadIdx.x;
    const float* src = (i < n4each) ? a : b;
    int ii = (i < n4each) ? i : i - n4each;
    float4 v = ((const float4*)src)[ii];
    __half hh[4];
    hh[0] = __float2half_rn(v.x); hh[1] = __float2half_rn(v.y);
    hh[2] = __float2half_rn(v.z); hh[3] = __float2half_rn(v.w);
    ((uint2*)h)[i] = *(uint2*)hh;
}

__global__ __launch_bounds__(256) void round_k(
    const float* __restrict__ src, __half* __restrict__ h, int n4)
{
    int i = blockIdx.x * 256 + threadIdx.x;
    if (i >= n4) return;
    float4 v = ((const float4*)src)[i];
    __half hh[4];
    hh[0] = __float2half_rn(v.x); hh[1] = __float2half_rn(v.y);
    hh[2] = __float2half_rn(v.z); hh[3] = __float2half_rn(v.w);
    ((uint2*)h)[i] = *(uint2*)hh;
}

// transpose + round: src [K][N] fp32 -> th [N][K] fp16
__global__ __launch_bounds__(256) void tround_k(
    const float* __restrict__ src, __half* __restrict__ th, int K, int N)
{
    __shared__ float tile[32][33];
    const int n0 = blockIdx.x * 32, k0 = blockIdx.y * 32;
    const int tx = threadIdx.x & 31, ty0 = threadIdx.x >> 5;
#pragma unroll
    for (int it = 0; it < 4; ++it) {
        int ty = ty0 + it * 8;
        tile[ty][tx] = src[(size_t)(k0 + ty) * N + n0 + tx];
    }
    __syncthreads();
#pragma unroll
    for (int it = 0; it < 4; ++it) {
        int ty = ty0 + it * 8;
        th[(size_t)(n0 + ty) * K + k0 + tx] = __float2half_rn(tile[tx][ty]);
    }
}

// per-head V transpose: g_V [bn][j][d] fp32 -> g_Vth [bn][d][j] fp16
__global__ __launch_bounds__(256) void vtrans_k()
{
    __shared__ float tile[64][65];
    const int j0 = blockIdx.x * 64;
    const int bn = blockIdx.y;
    const int tid = threadIdx.x;
#pragma unroll
    for (int it = 0; it < 16; ++it) {
        int idx = tid + it * 256;
        int j = idx >> 6, d = idx & 63;
        tile[j][d] = g_V[((size_t)bn * 1024 + j0 + j) * 64 + d];
    }
    __syncthreads();
#pragma unroll
    for (int it = 0; it < 16; ++it) {
        int idx = tid + it * 256;
        int d = idx >> 6, j = idx & 63;
        g_Vth[((size_t)bn * 64 + d) * 1024 + j0 + j] = __float2half_rn(tile[j][d]);
    }
}

// ---------------- fp16 HMMA GEMM (1 MMA), tile 128x128, BK=64, 3-stage ----------------
#define GSTG 32768
#define GTC_SMEM (3*GSTG)

template<int MODE>
__global__ __launch_bounds__(256, 1) void gemm_hf(
    const __half* __restrict__ Ah, const __half* __restrict__ Bh,
    float* __restrict__ C, const float* __restrict__ rwb, const float* __restrict__ rrb)
{
    const int m0 = blockIdx.y * 128;
    const int n0 = blockIdx.x * 128;
    if (MODE == 0 && n0 < 1024 && m0 < 8192) return;   // Q of mems: dead

    extern __shared__ char sm[];
    const int tid  = threadIdx.x;
    const int wid  = tid >> 5;
    const int lane = tid & 31;
    const int wm   = wid >> 2;
    const int wn   = wid & 3;
    const uint32_t smb = smem_u32(sm);

    float acc[4][4][4];
#pragma unroll
    for (int i = 0; i < 4; i++)
#pragma unroll
        for (int j = 0; j < 4; j++)
#pragma unroll
            for (int q = 0; q < 4; q++) acc[i][j][q] = 0.f;

    const int lr = tid >> 3;
    const int lc = tid & 7;

    auto load_stage = [&](int c, int stg) {
        const int k0 = c * 64;
        const uint32_t base = smb + stg * GSTG;
#pragma unroll
        for (int it = 0; it < 4; ++it) {
            int r = lr + it * 32;
            uint32_t dst = base + sphys(r, lc);
            cpa16(dst,         Ah + (size_t)(m0 + r) * 1024 + k0 + lc * 8);
            cpa16(dst + 16384, Bh + (size_t)(n0 + r) * 1024 + k0 + lc * 8);
        }
        CPA_COMMIT();
    };

    auto compute = [&](int stg) {
        const uint32_t base = smb + stg * GSTG;
#pragma unroll
        for (int s = 0; s < 4; ++s) {
            uint32_t ah[4][4], bh[4][2];
#pragma unroll
            for (int i = 0; i < 4; ++i) {
                int row = wm * 64 + i * 16 + (lane & 15);
                int ch  = s * 2 + (lane >> 4);
                ldsm4(ah[i], base + sphys(row, ch));
            }
#pragma unroll
            for (int j = 0; j < 4; ++j) {
                int row = wn * 32 + j * 8 + (lane & 7);
                int ch  = s * 2 + ((lane >> 3) & 1);
                ldsm2(bh[j], base + 16384u + sphys(row, ch));
            }
#pragma unroll
            for (int i = 0; i < 4; ++i)
#pragma unroll
                for (int j = 0; j < 4; ++j)
                    mma16816(acc[i][j], ah[i], bh[j]);
        }
    };

    load_stage(0, 0);
    load_stage(1, 1);
    load_stage(2, 2);
    int stg = 0;
#pragma unroll 1
    for (int c = 0; c < 16; ++c) {
        CPA_WAIT2();
        __syncthreads();
        compute(stg);
        __syncthreads();
        if (c + 3 < 16) load_stage(c + 3, stg);
        else            CPA_COMMIT();
        if (++stg == 3) stg = 0;
    }

    const int g   = lane >> 2;
    const int tig = lane & 3;

    auto storeC = [&](int m, int col, float v0, float v1) {
        if (MODE == 0) {
            int kl = m >> 4, bb = m & 15;
            int sec = col >> 10, hn = (col >> 6) & 15, d = col & 63;
            if (sec == 0) {
                if (kl >= MLEN) {
                    size_t o = ((size_t)(bb*NH+hn)*QLEN + (kl-MLEN))*DH + d;
                    float b0 = rwb[hn*64 + d], b1 = rwb[hn*64 + d + 1];
                    *(uint32_t*)&g_Qrwh[o] = f2h2(v0 + b0, v1 + b1);
                    float c0 = rrb[hn*64 + d], c1 = rrb[hn*64 + d + 1];
                    *(uint32_t*)&g_Qrrh[o] = f2h2(v0 + c0, v1 + c1);
                }
            } else if (sec == 1) {
                size_t o = ((size_t)(bb*NH+hn)*KLEN + kl)*DH + d;
                *(uint32_t*)&g_Khb[o] = f2h2(v0, v1);
            } else {
                *(float2*)&g_V[((size_t)(bb*NH+hn)*KLEN + kl)*DH + d] = make_float2(v0, v1);
            }
        } else if (MODE == 1) {
            int hn = col >> 6, d = col & 63;
            *(uint32_t*)&g_Rkh[((size_t)hn*KLEN + m)*DH + d] = f2h2(v0, v1);
        } else {
            *(float2*)&C[(size_t)m * 1024 + col] = make_float2(v0, v1);
        }
    };

#pragma unroll
    for (int i = 0; i < 4; ++i)
#pragma unroll
        for (int j = 0; j < 4; ++j) {
            int m   = m0 + wm*64 + i*16 + g;
            int col = n0 + wn*32 + j*8 + 2*tig;
            storeC(m,     col, acc[i][j][0], acc[i][j][1]);
            storeC(m + 8, col, acc[i][j][2], acc[i][j][3]);
        }
}

// ---------------- BD via HMMA: u-tile 128 ----------------
// smem: Q 8K | stage s (2x): Rk 16K  => 40K
#define BD_SMEM 40960
__global__ __launch_bounds__(128, 2) void bd_mma()
{
    extern __shared__ char sm[];
    const int i0 = blockIdx.x * 64;
    const int bn = blockIdx.y;
    const int nh = bn & 15;
    const int tid = threadIdx.x, wid = tid >> 5, lane = tid & 31;
    const uint32_t smb = smem_u32(sm);

    const int us = (i0 < 448) ? ((448 - i0) & ~127) : 0;   // 128-aligned start
    const int nt = (1024 - us) >> 7;

    const __half* Qh = g_Qrrh + ((size_t)bn*512 + i0) * 64;

#pragma unroll
    for (int it = 0; it < 4; ++it) {
        int idx = tid + it * 128;
        int r = idx >> 3, ch = idx & 7;
        cpa16(smb + sphys(r, ch), Qh + r*64 + ch*8);
    }
    CPA_COMMIT();

    auto load_rk = [&](int t) {
        if (t < nt) {
            int u0 = us + t * 128;
            uint32_t base = smb + 8192 + (t & 1) * 16384;
#pragma unroll
            for (int it = 0; it < 8; ++it) {
                int idx = tid + it * 128;
                int r = idx >> 3, ch = idx & 7;
                cpa16(base + sphys(r, ch), g_Rkh + ((size_t)nh*1024 + u0 + r)*64 + ch*8);
            }
        }
        CPA_COMMIT();
    };
    load_rk(0);
    load_rk(1);

    uint32_t aq[4][4];
    bool afrag = false;

    const int g = lane >> 2, tig = lane & 3;
    const int r0 = i0 + wid * 16 + g;

#pragma unroll 1
    for (int t = 0; t < nt; ++t) {
        CPA_WAIT1();
        __syncthreads();
        if (!afrag) {
            afrag = true;
#pragma unroll
            for (int kc = 0; kc < 4; ++kc) {
                int row = wid * 16 + (lane & 15);
                int ch  = kc * 2 + (lane >> 4);
                ldsm4(aq[kc], smb + sphys(row, ch));
            }
        }
        const uint32_t base = smb + 8192 + (t & 1) * 16384;
        const int u0 = us + t * 128;
        __half* bd0 = g_BDh + ((size_t)bn*512 + r0) * 1024 + u0;
        __half* bd1 = bd0 + 8 * 1024;

#pragma unroll
        for (int jt = 0; jt < 16; ++jt) {
            float sa[4] = {0.f, 0.f, 0.f, 0.f};
            uint32_t kh[4][2], tmp[4];
#pragma unroll
            for (int kp = 0; kp < 2; ++kp) {
                int row = jt * 8 + (lane & 7);
                int ch  = kp * 4 + (lane >> 3);
                ldsm4(tmp, base + sphys(row, ch));
                kh[kp*2][0] = tmp[0]; kh[kp*2][1] = tmp[1];
                kh[kp*2+1][0] = tmp[2]; kh[kp*2+1][1] = tmp[3];
            }
#pragma unroll
            for (int kc = 0; kc < 4; ++kc)
                mma16816(sa, aq[kc], kh[kc]);
            int uc = jt * 8 + 2 * tig;
            *(__half2*)(bd0 + uc) = __floats2half2_rn(sa[0], sa[1]);
            *(__half2*)(bd1 + uc) = __floats2half2_rn(sa[2], sa[3]);
        }
        __syncthreads();
        load_rk(t + 2);
    }
}

// ---------------- fused attention, j-tile 128 ----------------
// smem: Q 8K | stage s (2x): K 16K | V 16K (two 64-j panels)  => 72K
#define ATT_SMEM 73728
__global__ __launch_bounds__(128, 2) void attn_mma()
{
    extern __shared__ char sm[];
    const int i0 = blockIdx.x * 64;
    const int bn = blockIdx.y;
    const int b = bn >> 4, nh = bn & 15;
    const int tid = threadIdx.x, wid = tid >> 5, lane = tid & 31;
    const uint32_t smb = smem_u32(sm);

    const int nt = (i0 + 576 + 127) >> 7;     // 128-wide j tiles

    const __half* Qh = g_Qrwh + ((size_t)bn*512 + i0) * 64;

#pragma unroll
    for (int it = 0; it < 4; ++it) {
        int idx = tid + it * 128;
        int r = idx >> 3, ch = idx & 7;
        cpa16(smb + sphys(r, ch), Qh + r*64 + ch*8);
    }

    auto load_kv = [&](int t) {
        if (t < nt) {
            int j0 = t * 128;
            uint32_t base = smb + 8192 + (t & 1) * 32768;
            // K: 128 j-rows x 64 d (16K)
#pragma unroll
            for (int it = 0; it < 8; ++it) {
                int idx = tid + it * 128;
                int r = idx >> 3, ch = idx & 7;
                cpa16(base + sphys(r, ch), g_Khb + ((size_t)bn*1024 + j0 + r) * 64 + ch*8);
            }
            // V^T: 64 d-rows x 128 j, as two 64-j panels of 8K
#pragma unroll
            for (int it = 0; it < 8; ++it) {
                int idx = tid + it * 128;          // 0..1023
                int p = idx >> 9;                  // panel 0/1
                int w2 = idx & 511;
                int d = w2 >> 3, ch = w2 & 7;
                cpa16(base + 16384 + p*8192 + sphys(d, ch),
                      g_Vth + ((size_t)bn*64 + d) * 1024 + j0 + p*64 + ch*8);
            }
        }
        CPA_COMMIT();
    };
    load_kv(0);   // commits Q + KV0 together
    load_kv(1);

    uint32_t aq[4][4];
    bool afrag = false;

    const int g = lane >> 2, tig = lane & 3;
    const int r0 = i0 + wid * 16 + g;
    const int r1 = r0 + 8;
    const __half* bd0 = g_BDh + ((size_t)bn*512 + r0) * 1024;
    const __half* bd1 = bd0 + 8 * 1024;

    float mi0 = -1e30f, mi1 = -1e30f, li0 = 0.f, li1 = 0.f;
    float oacc[8][4];
#pragma unroll
    for (int dt = 0; dt < 8; ++dt)
#pragma unroll
        for (int q = 0; q < 4; ++q) oacc[dt][q] = 0.f;

#pragma unroll 1
    for (int t = 0; t < nt; ++t) {
        CPA_WAIT1();
        __syncthreads();
        if (!afrag) {
            afrag = true;
#pragma unroll
            for (int kc = 0; kc < 4; ++kc) {
                int row = wid * 16 + (lane & 15);
                int ch  = kc * 2 + (lane >> 4);
                ldsm4(aq[kc], smb + sphys(row, ch));
            }
        }
        const uint32_t kbase = smb + 8192 + (t & 1) * 32768;
        const int j0 = t * 128;

        // ---- S = Q·K^T over 128 cols ----
        float sa[16][4];
#pragma unroll
        for (int jt = 0; jt < 16; ++jt) {
            sa[jt][0] = sa[jt][1] = sa[jt][2] = sa[jt][3] = 0.f;
            uint32_t kh[4][2], tmp[4];
#pragma unroll
            for (int kp = 0; kp < 2; ++kp) {
                int row = jt * 8 + (lane & 7);
                int ch  = kp * 4 + (lane >> 3);
                ldsm4(tmp, kbase + sphys(row, ch));
                kh[kp*2][0] = tmp[0]; kh[kp*2][1] = tmp[1];
                kh[kp*2+1][0] = tmp[2]; kh[kp*2+1][1] = tmp[3];
            }
#pragma unroll
            for (int kc = 0; kc < 4; ++kc)
                mma16816(sa[jt], aq[kc], kh[kc]);
        }

        // ---- + BD, scale, mask ----
#pragma unroll
        for (int jt = 0; jt < 16; ++jt) {
            int j = j0 + jt * 8 + 2 * tig;
            sa[jt][0] = (j     <= r0 + 512) ? (sa[jt][0] + __half2float(bd0[j + 511 - r0])) * 0.125f : -1e30f;
            sa[jt][1] = (j + 1 <= r0 + 512) ? (sa[jt][1] + __half2float(bd0[j + 512 - r0])) * 0.125f : -1e30f;
            sa[jt][2] = (j     <= r1 + 512) ? (sa[jt][2] + __half2float(bd1[j + 511 - r1])) * 0.125f : -1e30f;
            sa[jt][3] = (j + 1 <= r1 + 512) ? (sa[jt][3] + __half2float(bd1[j + 512 - r1])) * 0.125f : -1e30f;
        }

        // ---- online softmax over 128 cols ----
        float m0 = -1e30f, m1 = -1e30f;
#pragma unroll
        for (int jt = 0; jt < 16; ++jt) {
            m0 = fmaxf(m0, fmaxf(sa[jt][0], sa[jt][1]));
            m1 = fmaxf(m1, fmaxf(sa[jt][2], sa[jt][3]));
        }
        m0 = fmaxf(m0, __shfl_xor_sync(0xffffffffu, m0, 1));
        m0 = fmaxf(m0, __shfl_xor_sync(0xffffffffu, m0, 2));
        m1 = fmaxf(m1, __shfl_xor_sync(0xffffffffu, m1, 1));
        m1 = fmaxf(m1, __shfl_xor_sync(0xffffffffu, m1, 2));
        float mn0 = fmaxf(mi0, m0), mn1 = fmaxf(mi1, m1);
        float al0 = __expf(mi0 - mn0), al1 = __expf(mi1 - mn1);
        mi0 = mn0; mi1 = mn1;
        float s0 = 0.f, s1 = 0.f;
#pragma unroll
        for (int jt = 0; jt < 16; ++jt) {
            sa[jt][0] = __expf(sa[jt][0] - mn0); s0 += sa[jt][0];
            sa[jt][1] = __expf(sa[jt][1] - mn0); s0 += sa[jt][1];
            sa[jt][2] = __expf(sa[jt][2] - mn1); s1 += sa[jt][2];
            sa[jt][3] = __expf(sa[jt][3] - mn1); s1 += sa[jt][3];
        }
        s0 += __shfl_xor_sync(0xffffffffu, s0, 1);
        s0 += __shfl_xor_sync(0xffffffffu, s0, 2);
        s1 += __shfl_xor_sync(0xffffffffu, s1, 1);
        s1 += __shfl_xor_sync(0xffffffffu, s1, 2);
        li0 = li0 * al0 + s0;
        li1 = li1 * al1 + s1;
#pragma unroll
        for (int dt = 0; dt < 8; ++dt) {
            oacc[dt][0] *= al0; oacc[dt][1] *= al0;
            oacc[dt][2] *= al1; oacc[dt][3] *= al1;
        }

        // ---- pack P (fp16, 128-wide) ----
        uint32_t pf[8][4];
#pragma unroll
        for (int kc = 0; kc < 8; ++kc) {
            pf[kc][0] = f2h2(sa[2*kc][0],   sa[2*kc][1]);
            pf[kc][1] = f2h2(sa[2*kc][2],   sa[2*kc][3]);
            pf[kc][2] = f2h2(sa[2*kc+1][0], sa[2*kc+1][1]);
            pf[kc][3] = f2h2(sa[2*kc+1][2], sa[2*kc+1][3]);
        }

        // ---- O += P · V (K=128) ----
#pragma unroll
        for (int dt = 0; dt < 8; ++dt) {
            uint32_t vh[8][2], tmp[4];
#pragma unroll
            for (int kp = 0; kp < 4; ++kp) {
                int p   = kp >> 1;
                int chp = (kp & 1) * 4 + (lane >> 3);
                int row = dt * 8 + (lane & 7);
                ldsm4(tmp, kbase + 16384 + p*8192 + sphys(row, chp));
                vh[kp*2][0] = tmp[0]; vh[kp*2][1] = tmp[1];
                vh[kp*2+1][0] = tmp[2]; vh[kp*2+1][1] = tmp[3];
            }
#pragma unroll
            for (int kc = 0; kc < 8; ++kc)
                mma16816(oacc[dt], pf[kc], vh[kc]);
        }
        __syncthreads();
        load_kv(t + 2);
    }

    // ---- store AV as fp16 ----
    float inv0 = 1.f / li0, inv1 = 1.f / li1;
#pragma unroll
    for (int dt = 0; dt < 8; ++dt) {
        int d = nh * 64 + dt * 8 + 2 * tig;
        *(uint32_t*)&g_AVh[((size_t)r0 * 16 + b) * 1024 + d] =
            f2h2(oacc[dt][0] * inv0, oacc[dt][1] * inv0);
        *(uint32_t*)&g_AVh[((size_t)r1 * 16 + b) * 1024 + d] =
            f2h2(oacc[dt][2] * inv1, oacc[dt][3] * inv1);
    }
}

// ---------------- residual + layernorm (warp-shuffle reductions) ----------------
__global__ __launch_bounds__(256) void ln_kernel(
    const float* __restrict__ w, const float* __restrict__ gamma,
    const float* __restrict__ beta, float* __restrict__ out)
{
    const int row = blockIdx.x;
    const int tid = threadIdx.x;
    const int lane = tid & 31, wid = tid >> 5;
    __shared__ float wred[8];
    const float* wrow = w   + (size_t)row * 1024;
    float*       orow = out + (size_t)row * 1024;

    float x[4];
    float sum = 0.f;
#pragma unroll
    for (int l = 0; l < 4; l++) {
        int c = tid + l*256;
        x[l] = wrow[c] + orow[c];
        sum += x[l];
    }
#pragma unroll
    for (int off = 16; off; off >>= 1) sum += __shfl_xor_sync(0xffffffffu, sum, off);
    if (lane == 0) wred[wid] = sum;
    __syncthreads();
    float tot = 0.f;
#pragma unroll
    for (int q = 0; q < 8; ++q) tot += wred[q];
    float mu = tot * (1.f/1024.f);
    __syncthreads();

    float vs = 0.f;
#pragma unroll
    for (int l = 0; l < 4; l++) { float dx = x[l] - mu; vs += dx*dx; }
#pragma unroll
    for (int off = 16; off; off >>= 1) vs += __shfl_xor_sync(0xffffffffu, vs, off);
    if (lane == 0) wred[wid] = vs;
    __syncthreads();
    float vtot = 0.f;
#pragma unroll
    for (int q = 0; q < 8; ++q) vtot += wred[q];
    float rstd = rsqrtf(vtot * (1.f/1024.f) + 1e-6f);

#pragma unroll
    for (int l = 0; l < 4; l++) {
        int c = tid + l*256;
        orow[c] = (x[l] - mu) * rstd * gamma[c] + beta[c];
    }
}

// ---------------- launch ----------------
extern "C" void kernel_launch(void* const* d_in, const int* in_sizes, int n_in,
                              void* d_out, int out_size)
{
    const float* w      = (const float*)d_in[0];
    const float* r      = (const float*)d_in[1];
    const float* mems   = (const float*)d_in[3];
    const float* qkvw   = (const float*)d_in[4];
    const float* rw     = (const float*)d_in[5];
    const float* ow     = (const float*)d_in[6];
    const float* rrb    = (const float*)d_in[7];
    const float* rwbias = (const float*)d_in[8];
    const float* gamma  = (const float*)d_in[9];
    const float* beta   = (const float*)d_in[10];
    float* out = (float*)d_out;

    __half *Ah, *Wth, *R2h, *RWth, *OWth, *AVh;
    cudaGetSymbolAddress((void**)&Ah,  g_Ah);
    cudaGetSymbolAddress((void**)&Wth, g_Wth);
    cudaGetSymbolAddress((void**)&R2h, g_R2h);
    cudaGetSymbolAddress((void**)&RWth,g_RWth);
    cudaGetSymbolAddress((void**)&OWth,g_OWth);
    cudaGetSymbolAddress((void**)&AVh, g_AVh);

    cudaFuncSetAttribute(gemm_hf<0>, cudaFuncAttributeMaxDynamicSharedMemorySize, GTC_SMEM);
    cudaFuncSetAttribute(gemm_hf<1>, cudaFuncAttributeMaxDynamicSharedMemorySize, GTC_SMEM);
    cudaFuncSetAttribute(gemm_hf<2>, cudaFuncAttributeMaxDynamicSharedMemorySize, GTC_SMEM);
    cudaFuncSetAttribute(bd_mma,   cudaFuncAttributeMaxDynamicSharedMemorySize, BD_SMEM);
    cudaFuncSetAttribute(attn_mma, cudaFuncAttributeMaxDynamicSharedMemorySize, ATT_SMEM);

    // prep
    round2_k<<<16384, 256>>>(mems, w, Ah, 2097152);
    tround_k<<<dim3(96, 32), 256>>>(qkvw, Wth, 1024, 3072);
    round_k <<<1024, 256>>>(r, R2h, 262144);
    tround_k<<<dim3(32, 32), 256>>>(rw, RWth, 1024, 1024);
    tround_k<<<dim3(32, 32), 256>>>(ow, OWth, 1024, 1024);

    // GEMMs (epilogues write attention operands directly)
    gemm_hf<0><<<dim3(24, 128), 256, GTC_SMEM>>>(Ah, Wth, nullptr, rwbias, rrb);
    gemm_hf<1><<<dim3(8, 8),    256, GTC_SMEM>>>(R2h, RWth, nullptr, nullptr, nullptr);
    vtrans_k<<<dim3(16, 256), 256>>>();

    // BD + attention
    bd_mma  <<<dim3(8, 256), 128, BD_SMEM>>>();
    attn_mma<<<dim3(8, 256), 128, ATT_SMEM>>>();

    // output projection + layernorm
    gemm_hf<2><<<dim3(8, 64),   256, GTC_SMEM>>>(AVh, OWth, out, nullptr, nullptr);
    ln_kernel  <<<8192, 256>>>(w, gamma, beta, out);
}

// round 12
// speedup vs baseline: 1.2392x; 1.2392x over previous
#include <cuda_runtime.h>
#include <cuda_fp16.h>
#include <math.h>
#include <stdint.h>

#define QLEN 512
#define MLEN 512
#define KLEN 1024
#define BSZ  16
#define NH   16
#define DH   64
#define DM   1024
#define HID  1024

// ---------------- scratch ----------------
__device__ float  g_V  [(size_t)BSZ*NH*KLEN*DH];          // fp32 V (for transpose)
__device__ __half g_BDh[(size_t)BSZ*NH*QLEN*KLEN];        // BD scores fp16

__device__ __half g_Ah [(size_t)16384*1024];              // cat(mems,w) fp16
__device__ __half g_Wth[(size_t)3072*1024];               // qkv_w^T fp16
__device__ __half g_R2h[(size_t)1024*1024];               // r fp16
__device__ __half g_RWth[(size_t)1024*1024];              // r_w^T fp16
__device__ __half g_OWth[(size_t)1024*1024];              // o_w^T fp16
__device__ __half g_AVh[(size_t)8192*1024];               // attn_vec fp16

__device__ __half g_Qrwh[(size_t)BSZ*NH*QLEN*DH];         // (Q+rw_bias) fp16
__device__ __half g_Qrrh[(size_t)BSZ*NH*QLEN*DH];         // (Q+rr_bias) fp16
__device__ __half g_Khb [(size_t)BSZ*NH*KLEN*DH];         // K fp16
__device__ __half g_Vth [(size_t)BSZ*NH*DH*KLEN];         // V^T fp16
__device__ __half g_Rkh [(size_t)NH*KLEN*DH];             // Rk fp16

// ================= helpers =================
__device__ __forceinline__ uint32_t smem_u32(const void* p) {
    uint32_t a;
    asm("{ .reg .u64 t; cvta.to.shared.u64 t, %1; cvt.u32.u64 %0, t; }" : "=r"(a) : "l"(p));
    return a;
}
__device__ __forceinline__ void ldsm4(uint32_t a[4], uint32_t addr) {
    asm volatile("ldmatrix.sync.aligned.m8n8.x4.shared.b16 {%0,%1,%2,%3}, [%4];"
                 : "=r"(a[0]), "=r"(a[1]), "=r"(a[2]), "=r"(a[3]) : "r"(addr));
}
__device__ __forceinline__ void ldsm2(uint32_t b[2], uint32_t addr) {
    asm volatile("ldmatrix.sync.aligned.m8n8.x2.shared.b16 {%0,%1}, [%2];"
                 : "=r"(b[0]), "=r"(b[1]) : "r"(addr));
}
__device__ __forceinline__ void mma16816(float c[4], const uint32_t a[4], const uint32_t b[2]) {
    asm volatile("mma.sync.aligned.m16n8k16.row.col.f32.f16.f16.f32 "
        "{%0,%1,%2,%3}, {%4,%5,%6,%7}, {%8,%9}, {%0,%1,%2,%3};"
        : "+f"(c[0]), "+f"(c[1]), "+f"(c[2]), "+f"(c[3])
        : "r"(a[0]), "r"(a[1]), "r"(a[2]), "r"(a[3]), "r"(b[0]), "r"(b[1]));
}
__device__ __forceinline__ void cpa16(uint32_t dst, const void* src) {
    asm volatile("cp.async.cg.shared.global [%0], [%1], 16;" :: "r"(dst), "l"(src));
}
#define CPA_COMMIT() asm volatile("cp.async.commit_group;")
#define CPA_WAIT1()  asm volatile("cp.async.wait_group 1;")
#define CPA_WAIT2()  asm volatile("cp.async.wait_group 2;")

__device__ __forceinline__ uint32_t f2h2(float a, float b) {
    __half2 t = __floats2half2_rn(a, b);
    return *reinterpret_cast<uint32_t*>(&t);
}
__device__ __forceinline__ uint32_t sphys(int r, int ch) {   // 128B rows, XOR swizzle
    return (uint32_t)(r * 128 + ((ch ^ (r & 7)) << 4));
}

// ---------------- prep kernels ----------------
__global__ __launch_bounds__(256) void round2_k(
    const float* __restrict__ a, const float* __restrict__ b,
    __half* __restrict__ h, int n4each)
{
    int i = blockIdx.x * 256 + threadIdx.x;
    const float* src = (i < n4each) ? a : b;
    int ii = (i < n4each) ? i : i - n4each;
    float4 v = ((const float4*)src)[ii];
    __half hh[4];
    hh[0] = __float2half_rn(v.x); hh[1] = __float2half_rn(v.y);
    hh[2] = __float2half_rn(v.z); hh[3] = __float2half_rn(v.w);
    ((uint2*)h)[i] = *(uint2*)hh;
}

__global__ __launch_bounds__(256) void round_k(
    const float* __restrict__ src, __half* __restrict__ h, int n4)
{
    int i = blockIdx.x * 256 + threadIdx.x;
    if (i >= n4) return;
    float4 v = ((const float4*)src)[i];
    __half hh[4];
    hh[0] = __float2half_rn(v.x); hh[1] = __float2half_rn(v.y);
    hh[2] = __float2half_rn(v.z); hh[3] = __float2half_rn(v.w);
    ((uint2*)h)[i] = *(uint2*)hh;
}

// transpose + round: src [K][N] fp32 -> th [N][K] fp16
__global__ __launch_bounds__(256) void tround_k(
    const float* __restrict__ src, __half* __restrict__ th, int K, int N)
{
    __shared__ float tile[32][33];
    const int n0 = blockIdx.x * 32, k0 = blockIdx.y * 32;
    const int tx = threadIdx.x & 31, ty0 = threadIdx.x >> 5;
#pragma unroll
    for (int it = 0; it < 4; ++it) {
        int ty = ty0 + it * 8;
        tile[ty][tx] = src[(size_t)(k0 + ty) * N + n0 + tx];
    }
    __syncthreads();
#pragma unroll
    for (int it = 0; it < 4; ++it) {
        int ty = ty0 + it * 8;
        th[(size_t)(n0 + ty) * K + k0 + tx] = __float2half_rn(tile[tx][ty]);
    }
}

// per-head V transpose: g_V [bn][j][d] fp32 -> g_Vth [bn][d][j] fp16
__global__ __launch_bounds__(256) void vtrans_k()
{
    __shared__ float tile[64][65];
    const int j0 = blockIdx.x * 64;
    const int bn = blockIdx.y;
    const int tid = threadIdx.x;
#pragma unroll
    for (int it = 0; it < 16; ++it) {
        int idx = tid + it * 256;
        int j = idx >> 6, d = idx & 63;
        tile[j][d] = g_V[((size_t)bn * 1024 + j0 + j) * 64 + d];
    }
    __syncthreads();
#pragma unroll
    for (int it = 0; it < 16; ++it) {
        int idx = tid + it * 256;
        int d = idx >> 6, j = idx & 63;
        g_Vth[((size_t)bn * 64 + d) * 1024 + j0 + j] = __float2half_rn(tile[j][d]);
    }
}

// ---------------- fp16 HMMA GEMM (1 MMA), tile 128x128, BK=64, 3-stage ----------------
#define GSTG 32768
#define GTC_SMEM (3*GSTG)

template<int MODE>
__global__ __launch_bounds__(256, 1) void gemm_hf(
    const __half* __restrict__ Ah, const __half* __restrict__ Bh,
    float* __restrict__ C, const float* __restrict__ rwb, const float* __restrict__ rrb)
{
    const int m0 = blockIdx.y * 128;
    const int n0 = blockIdx.x * 128;
    if (MODE == 0 && n0 < 1024 && m0 < 8192) return;   // Q of mems: dead

    extern __shared__ char sm[];
    const int tid  = threadIdx.x;
    const int wid  = tid >> 5;
    const int lane = tid & 31;
    const int wm   = wid >> 2;
    const int wn   = wid & 3;
    const uint32_t smb = smem_u32(sm);

    float acc[4][4][4];
#pragma unroll
    for (int i = 0; i < 4; i++)
#pragma unroll
        for (int j = 0; j < 4; j++)
#pragma unroll
            for (int q = 0; q < 4; q++) acc[i][j][q] = 0.f;

    const int lr = tid >> 3;
    const int lc = tid & 7;

    auto load_stage = [&](int c, int stg) {
        const int k0 = c * 64;
        const uint32_t base = smb + stg * GSTG;
#pragma unroll
        for (int it = 0; it < 4; ++it) {
            int r = lr + it * 32;
            uint32_t dst = base + sphys(r, lc);
            cpa16(dst,         Ah + (size_t)(m0 + r) * 1024 + k0 + lc * 8);
            cpa16(dst + 16384, Bh + (size_t)(n0 + r) * 1024 + k0 + lc * 8);
        }
        CPA_COMMIT();
    };

    auto compute = [&](int stg) {
        const uint32_t base = smb + stg * GSTG;
#pragma unroll
        for (int s = 0; s < 4; ++s) {
            uint32_t ah[4][4], bh[4][2];
#pragma unroll
            for (int i = 0; i < 4; ++i) {
                int row = wm * 64 + i * 16 + (lane & 15);
                int ch  = s * 2 + (lane >> 4);
                ldsm4(ah[i], base + sphys(row, ch));
            }
#pragma unroll
            for (int j = 0; j < 4; ++j) {
                int row = wn * 32 + j * 8 + (lane & 7);
                int ch  = s * 2 + ((lane >> 3) & 1);
                ldsm2(bh[j], base + 16384u + sphys(row, ch));
            }
#pragma unroll
            for (int i = 0; i < 4; ++i)
#pragma unroll
                for (int j = 0; j < 4; ++j)
                    mma16816(acc[i][j], ah[i], bh[j]);
        }
    };

    load_stage(0, 0);
    load_stage(1, 1);
    load_stage(2, 2);
    int stg = 0;
#pragma unroll 1
    for (int c = 0; c < 16; ++c) {
        CPA_WAIT2();
        __syncthreads();
        compute(stg);
        __syncthreads();
        if (c + 3 < 16) load_stage(c + 3, stg);
        else            CPA_COMMIT();
        if (++stg == 3) stg = 0;
    }

    const int g   = lane >> 2;
    const int tig = lane & 3;

    auto storeC = [&](int m, int col, float v0, float v1) {
        if (MODE == 0) {
            int kl = m >> 4, bb = m & 15;
            int sec = col >> 10, hn = (col >> 6) & 15, d = col & 63;
            if (sec == 0) {
                if (kl >= MLEN) {
                    size_t o = ((size_t)(bb*NH+hn)*QLEN + (kl-MLEN))*DH + d;
                    float b0 = rwb[hn*64 + d], b1 = rwb[hn*64 + d + 1];
                    *(uint32_t*)&g_Qrwh[o] = f2h2(v0 + b0, v1 + b1);
                    float c0 = rrb[hn*64 + d], c1 = rrb[hn*64 + d + 1];
                    *(uint32_t*)&g_Qrrh[o] = f2h2(v0 + c0, v1 + c1);
                }
            } else if (sec == 1) {
                size_t o = ((size_t)(bb*NH+hn)*KLEN + kl)*DH + d;
                *(uint32_t*)&g_Khb[o] = f2h2(v0, v1);
            } else {
                *(float2*)&g_V[((size_t)(bb*NH+hn)*KLEN + kl)*DH + d] = make_float2(v0, v1);
            }
        } else if (MODE == 1) {
            int hn = col >> 6, d = col & 63;
            *(uint32_t*)&g_Rkh[((size_t)hn*KLEN + m)*DH + d] = f2h2(v0, v1);
        } else {
            *(float2*)&C[(size_t)m * 1024 + col] = make_float2(v0, v1);
        }
    };

#pragma unroll
    for (int i = 0; i < 4; ++i)
#pragma unroll
        for (int j = 0; j < 4; ++j) {
            int m   = m0 + wm*64 + i*16 + g;
            int col = n0 + wn*32 + j*8 + 2*tig;
            storeC(m,     col, acc[i][j][0], acc[i][j][1]);
            storeC(m + 8, col, acc[i][j][2], acc[i][j][3]);
        }
}

// ---------------- BD via HMMA (1 MMA): BD[i][u] = (q+rrb)·rk  (R9 proven) ----------------
// smem: Q 8K | stage s (2x): Rk 8K  => 24K
#define BD_SMEM 24576
__global__ __launch_bounds__(128, 2) void bd_mma()
{
    extern __shared__ char sm[];
    const int i0 = blockIdx.x * 64;
    const int bn = blockIdx.y;
    const int nh = bn & 15;
    const int tid = threadIdx.x, wid = tid >> 5, lane = tid & 31;
    const uint32_t smb = smem_u32(sm);

    const int us = (448 - i0) > 0 ? (448 - i0) : 0;
    const int nt = (1024 - us) >> 6;

    const __half* Qh = g_Qrrh + ((size_t)bn*512 + i0) * 64;

#pragma unroll
    for (int it = 0; it < 4; ++it) {
        int idx = tid + it * 128;
        int r = idx >> 3, ch = idx & 7;
        cpa16(smb + sphys(r, ch), Qh + r*64 + ch*8);
    }
    CPA_COMMIT();

    auto load_rk = [&](int t) {
        if (t < nt) {
            int u0 = us + t * 64;
            uint32_t base = smb + 8192 + (t & 1) * 8192;
#pragma unroll
            for (int it = 0; it < 4; ++it) {
                int idx = tid + it * 128;
                int r = idx >> 3, ch = idx & 7;
                cpa16(base + sphys(r, ch), g_Rkh + ((size_t)nh*1024 + u0 + r)*64 + ch*8);
            }
        }
        CPA_COMMIT();
    };
    load_rk(0);
    load_rk(1);

    uint32_t aq[4][4];
    bool afrag = false;

    const int g = lane >> 2, tig = lane & 3;
    const int r0 = i0 + wid * 16 + g;

#pragma unroll 1
    for (int t = 0; t < nt; ++t) {
        CPA_WAIT1();
        __syncthreads();
        if (!afrag) {
            afrag = true;
#pragma unroll
            for (int kc = 0; kc < 4; ++kc) {
                int row = wid * 16 + (lane & 15);
                int ch  = kc * 2 + (lane >> 4);
                ldsm4(aq[kc], smb + sphys(row, ch));
            }
        }
        const uint32_t base = smb + 8192 + (t & 1) * 8192;
        const int u0 = us + t * 64;
        __half* bd0 = g_BDh + ((size_t)bn*512 + r0) * 1024 + u0;
        __half* bd1 = bd0 + 8 * 1024;

#pragma unroll
        for (int jt = 0; jt < 8; ++jt) {
            float sa[4] = {0.f, 0.f, 0.f, 0.f};
            uint32_t kh[4][2], tmp[4];
#pragma unroll
            for (int kp = 0; kp < 2; ++kp) {
                int row = jt * 8 + (lane & 7);
                int ch  = kp * 4 + (lane >> 3);
                ldsm4(tmp, base + sphys(row, ch));
                kh[kp*2][0] = tmp[0]; kh[kp*2][1] = tmp[1];
                kh[kp*2+1][0] = tmp[2]; kh[kp*2+1][1] = tmp[3];
            }
#pragma unroll
            for (int kc = 0; kc < 4; ++kc)
                mma16816(sa, aq[kc], kh[kc]);
            int uc = jt * 8 + 2 * tig;
            *(__half2*)(bd0 + uc) = __floats2half2_rn(sa[0], sa[1]);
            *(__half2*)(bd1 + uc) = __floats2half2_rn(sa[2], sa[3]);
        }
        __syncthreads();
        load_rk(t + 2);
    }
}

// ---------------- fused attention via HMMA + online softmax (R9 proven) ----------------
// smem: Q 8K | stage s (2x): K 8K | V 8K  => 40K
#define ATT_SMEM 40960
__global__ __launch_bounds__(128, 2) void attn_mma()
{
    extern __shared__ char sm[];
    const int i0 = blockIdx.x * 64;
    const int bn = blockIdx.y;
    const int b = bn >> 4, nh = bn & 15;
    const int tid = threadIdx.x, wid = tid >> 5, lane = tid & 31;
    const uint32_t smb = smem_u32(sm);

    const int nt = (i0 >> 6) + 9;

    const __half* Qh = g_Qrwh + ((size_t)bn*512 + i0) * 64;

#pragma unroll
    for (int it = 0; it < 4; ++it) {
        int idx = tid + it * 128;
        int r = idx >> 3, ch = idx & 7;
        cpa16(smb + sphys(r, ch), Qh + r*64 + ch*8);
    }

    auto load_kv = [&](int t) {
        if (t < nt) {
            int j0 = t * 64;
            uint32_t base = smb + 8192 + (t & 1) * 16384;
#pragma unroll
            for (int it = 0; it < 4; ++it) {
                int idx = tid + it * 128;
                int r = idx >> 3, ch = idx & 7;
                cpa16(base + sphys(r, ch),        g_Khb + ((size_t)bn*1024 + j0 + r) * 64 + ch*8);
                cpa16(base + 8192 + sphys(r, ch), g_Vth + ((size_t)bn*64 + r) * 1024 + j0 + ch*8);
            }
        }
        CPA_COMMIT();
    };
    load_kv(0);   // commits Q + KV0 together
    load_kv(1);

    uint32_t aq[4][4];
    bool afrag = false;

    const int g = lane >> 2, tig = lane & 3;
    const int r0 = i0 + wid * 16 + g;
    const int r1 = r0 + 8;
    const __half* bd0 = g_BDh + ((size_t)bn*512 + r0) * 1024;
    const __half* bd1 = bd0 + 8 * 1024;

    float mi0 = -1e30f, mi1 = -1e30f, li0 = 0.f, li1 = 0.f;
    float oacc[8][4];
#pragma unroll
    for (int dt = 0; dt < 8; ++dt)
#pragma unroll
        for (int q = 0; q < 4; ++q) oacc[dt][q] = 0.f;

#pragma unroll 1
    for (int t = 0; t < nt; ++t) {
        CPA_WAIT1();
        __syncthreads();
        if (!afrag) {
            afrag = true;
#pragma unroll
            for (int kc = 0; kc < 4; ++kc) {
                int row = wid * 16 + (lane & 15);
                int ch  = kc * 2 + (lane >> 4);
                ldsm4(aq[kc], smb + sphys(row, ch));
            }
        }
        const uint32_t kbase = smb + 8192 + (t & 1) * 16384;
        const int j0 = t * 64;

        // ---- S = Q·K^T (1 MMA) ----
        float sa[8][4];
#pragma unroll
        for (int jt = 0; jt < 8; ++jt) {
            sa[jt][0] = sa[jt][1] = sa[jt][2] = sa[jt][3] = 0.f;
            uint32_t kh[4][2], tmp[4];
#pragma unroll
            for (int kp = 0; kp < 2; ++kp) {
                int row = jt * 8 + (lane & 7);
                int ch  = kp * 4 + (lane >> 3);
                ldsm4(tmp, kbase + sphys(row, ch));
                kh[kp*2][0] = tmp[0]; kh[kp*2][1] = tmp[1];
                kh[kp*2+1][0] = tmp[2]; kh[kp*2+1][1] = tmp[3];
            }
#pragma unroll
            for (int kc = 0; kc < 4; ++kc)
                mma16816(sa[jt], aq[kc], kh[kc]);
        }

        // ---- + BD, scale, mask ----
#pragma unroll
        for (int jt = 0; jt < 8; ++jt) {
            int j = j0 + jt * 8 + 2 * tig;
            sa[jt][0] = (j     <= r0 + 512) ? (sa[jt][0] + __half2float(bd0[j + 511 - r0])) * 0.125f : -1e30f;
            sa[jt][1] = (j + 1 <= r0 + 512) ? (sa[jt][1] + __half2float(bd0[j + 512 - r0])) * 0.125f : -1e30f;
            sa[jt][2] = (j     <= r1 + 512) ? (sa[jt][2] + __half2float(bd1[j + 511 - r1])) * 0.125f : -1e30f;
            sa[jt][3] = (j + 1 <= r1 + 512) ? (sa[jt][3] + __half2float(bd1[j + 512 - r1])) * 0.125f : -1e30f;
        }

        // ---- online softmax ----
        float m0 = -1e30f, m1 = -1e30f;
#pragma unroll
        for (int jt = 0; jt < 8; ++jt) {
            m0 = fmaxf(m0, fmaxf(sa[jt][0], sa[jt][1]));
            m1 = fmaxf(m1, fmaxf(sa[jt][2], sa[jt][3]));
        }
        m0 = fmaxf(m0, __shfl_xor_sync(0xffffffffu, m0, 1));
        m0 = fmaxf(m0, __shfl_xor_sync(0xffffffffu, m0, 2));
        m1 = fmaxf(m1, __shfl_xor_sync(0xffffffffu, m1, 1));
        m1 = fmaxf(m1, __shfl_xor_sync(0xffffffffu, m1, 2));
        float mn0 = fmaxf(mi0, m0), mn1 = fmaxf(mi1, m1);
        float al0 = __expf(mi0 - mn0), al1 = __expf(mi1 - mn1);
        mi0 = mn0; mi1 = mn1;
        float s0 = 0.f, s1 = 0.f;
#pragma unroll
        for (int jt = 0; jt < 8; ++jt) {
            sa[jt][0] = __expf(sa[jt][0] - mn0); s0 += sa[jt][0];
            sa[jt][1] = __expf(sa[jt][1] - mn0); s0 += sa[jt][1];
            sa[jt][2] = __expf(sa[jt][2] - mn1); s1 += sa[jt][2];
            sa[jt][3] = __expf(sa[jt][3] - mn1); s1 += sa[jt][3];
        }
        s0 += __shfl_xor_sync(0xffffffffu, s0, 1);
        s0 += __shfl_xor_sync(0xffffffffu, s0, 2);
        s1 += __shfl_xor_sync(0xffffffffu, s1, 1);
        s1 += __shfl_xor_sync(0xffffffffu, s1, 2);
        li0 = li0 * al0 + s0;
        li1 = li1 * al1 + s1;
#pragma unroll
        for (int dt = 0; dt < 8; ++dt) {
            oacc[dt][0] *= al0; oacc[dt][1] *= al0;
            oacc[dt][2] *= al1; oacc[dt][3] *= al1;
        }

        // ---- pack P (fp16) ----
        uint32_t pf[4][4];
#pragma unroll
        for (int kc = 0; kc < 4; ++kc) {
            pf[kc][0] = f2h2(sa[2*kc][0],   sa[2*kc][1]);
            pf[kc][1] = f2h2(sa[2*kc][2],   sa[2*kc][3]);
            pf[kc][2] = f2h2(sa[2*kc+1][0], sa[2*kc+1][1]);
            pf[kc][3] = f2h2(sa[2*kc+1][2], sa[2*kc+1][3]);
        }

        // ---- O += P · V (1 MMA) ----
        const uint32_t vbase = kbase + 8192;
#pragma unroll
        for (int dt = 0; dt < 8; ++dt) {
            uint32_t vh[4][2], tmp[4];
#pragma unroll
            for (int kp = 0; kp < 2; ++kp) {
                int row = dt * 8 + (lane & 7);
                int ch  = kp * 4 + (lane >> 3);
                ldsm4(tmp, vbase + sphys(row, ch));
                vh[kp*2][0] = tmp[0]; vh[kp*2][1] = tmp[1];
                vh[kp*2+1][0] = tmp[2]; vh[kp*2+1][1] = tmp[3];
            }
#pragma unroll
            for (int kc = 0; kc < 4; ++kc)
                mma16816(oacc[dt], pf[kc], vh[kc]);
        }
        __syncthreads();
        load_kv(t + 2);
    }

    // ---- store AV as fp16 ----
    float inv0 = 1.f / li0, inv1 = 1.f / li1;
#pragma unroll
    for (int dt = 0; dt < 8; ++dt) {
        int d = nh * 64 + dt * 8 + 2 * tig;
        *(uint32_t*)&g_AVh[((size_t)r0 * 16 + b) * 1024 + d] =
            f2h2(oacc[dt][0] * inv0, oacc[dt][1] * inv0);
        *(uint32_t*)&g_AVh[((size_t)r1 * 16 + b) * 1024 + d] =
            f2h2(oacc[dt][2] * inv1, oacc[dt][3] * inv1);
    }
}

// ---------------- residual + layernorm (warp-shuffle reductions) ----------------
__global__ __launch_bounds__(256) void ln_kernel(
    const float* __restrict__ w, const float* __restrict__ gamma,
    const float* __restrict__ beta, float* __restrict__ out)
{
    const int row = blockIdx.x;
    const int tid = threadIdx.x;
    const int lane = tid & 31, wid = tid >> 5;
    __shared__ float wred[8];
    const float* wrow = w   + (size_t)row * 1024;
    float*       orow = out + (size_t)row * 1024;

    float x[4];
    float sum = 0.f;
#pragma unroll
    for (int l = 0; l < 4; l++) {
        int c = tid + l*256;
        x[l] = wrow[c] + orow[c];
        sum += x[l];
    }
#pragma unroll
    for (int off = 16; off; off >>= 1) sum += __shfl_xor_sync(0xffffffffu, sum, off);
    if (lane == 0) wred[wid] = sum;
    __syncthreads();
    float tot = 0.f;
#pragma unroll
    for (int q = 0; q < 8; ++q) tot += wred[q];
    float mu = tot * (1.f/1024.f);
    __syncthreads();

    float vs = 0.f;
#pragma unroll
    for (int l = 0; l < 4; l++) { float dx = x[l] - mu; vs += dx*dx; }
#pragma unroll
    for (int off = 16; off; off >>= 1) vs += __shfl_xor_sync(0xffffffffu, vs, off);
    if (lane == 0) wred[wid] = vs;
    __syncthreads();
    float vtot = 0.f;
#pragma unroll
    for (int q = 0; q < 8; ++q) vtot += wred[q];
    float rstd = rsqrtf(vtot * (1.f/1024.f) + 1e-6f);

#pragma unroll
    for (int l = 0; l < 4; l++) {
        int c = tid + l*256;
        orow[c] = (x[l] - mu) * rstd * gamma[c] + beta[c];
    }
}

// ---------------- launch ----------------
extern "C" void kernel_launch(void* const* d_in, const int* in_sizes, int n_in,
                              void* d_out, int out_size)
{
    const float* w      = (const float*)d_in[0];
    const float* r      = (const float*)d_in[1];
    const float* mems   = (const float*)d_in[3];
    const float* qkvw   = (const float*)d_in[4];
    const float* rw     = (const float*)d_in[5];
    const float* ow     = (const float*)d_in[6];
    const float* rrb    = (const float*)d_in[7];
    const float* rwbias = (const float*)d_in[8];
    const float* gamma  = (const float*)d_in[9];
    const float* beta   = (const float*)d_in[10];
    float* out = (float*)d_out;

    __half *Ah, *Wth, *R2h, *RWth, *OWth, *AVh;
    cudaGetSymbolAddress((void**)&Ah,  g_Ah);
    cudaGetSymbolAddress((void**)&Wth, g_Wth);
    cudaGetSymbolAddress((void**)&R2h, g_R2h);
    cudaGetSymbolAddress((void**)&RWth,g_RWth);
    cudaGetSymbolAddress((void**)&OWth,g_OWth);
    cudaGetSymbolAddress((void**)&AVh, g_AVh);

    cudaFuncSetAttribute(gemm_hf<0>, cudaFuncAttributeMaxDynamicSharedMemorySize, GTC_SMEM);
    cudaFuncSetAttribute(gemm_hf<1>, cudaFuncAttributeMaxDynamicSharedMemorySize, GTC_SMEM);
    cudaFuncSetAttribute(gemm_hf<2>, cudaFuncAttributeMaxDynamicSharedMemorySize, GTC_SMEM);
    cudaFuncSetAttribute(bd_mma,   cudaFuncAttributeMaxDynamicSharedMemorySize, BD_SMEM);
    cudaFuncSetAttribute(attn_mma, cudaFuncAttributeMaxDynamicSharedMemorySize, ATT_SMEM);

    // prep
    round2_k<<<16384, 256>>>(mems, w, Ah, 2097152);
    tround_k<<<dim3(96, 32), 256>>>(qkvw, Wth, 1024, 3072);
    round_k <<<1024, 256>>>(r, R2h, 262144);
    tround_k<<<dim3(32, 32), 256>>>(rw, RWth, 1024, 1024);
    tround_k<<<dim3(32, 32), 256>>>(ow, OWth, 1024, 1024);

    // GEMMs (epilogues write attention operands directly)
    gemm_hf<0><<<dim3(24, 128), 256, GTC_SMEM>>>(Ah, Wth, nullptr, rwbias, rrb);
    gemm_hf<1><<<dim3(8, 8),    256, GTC_SMEM>>>(R2h, RWth, nullptr, nullptr, nullptr);
    vtrans_k<<<dim3(16, 256), 256>>>();

    // BD + attention
    bd_mma  <<<dim3(8, 256), 128, BD_SMEM>>>();
    attn_mma<<<dim3(8, 256), 128, ATT_SMEM>>>();

    // output projection + layernorm
    gemm_hf<2><<<dim3(8, 64),   256, GTC_SMEM>>>(AVh, OWth, out, nullptr, nullptr);
    ln_kernel  <<<8192, 256>>>(w, gamma, beta, out);
}

// round 13
// speedup vs baseline: 1.3187x; 1.0641x over previous
#include <cuda_runtime.h>
#include <cuda_fp16.h>
#include <math.h>
#include <stdint.h>

#define QLEN 512
#define MLEN 512
#define KLEN 1024
#define BSZ  16
#define NH   16
#define DH   64
#define DM   1024
#define HID  1024

// ---------------- scratch ----------------
__device__ float  g_V  [(size_t)BSZ*NH*KLEN*DH];          // fp32 V (for transpose)
__device__ __half g_BDh[(size_t)BSZ*NH*QLEN*KLEN];        // BD scores fp16

__device__ __half g_Ah [(size_t)16384*1024];              // cat(mems,w) fp16
__device__ __half g_Wth[(size_t)3072*1024];               // qkv_w^T fp16
__device__ __half g_R2h[(size_t)1024*1024];               // r fp16
__device__ __half g_RWth[(size_t)1024*1024];              // r_w^T fp16
__device__ __half g_OWth[(size_t)1024*1024];              // o_w^T fp16
__device__ __half g_AVh[(size_t)8192*1024];               // attn_vec fp16

__device__ __half g_Qrwh[(size_t)BSZ*NH*QLEN*DH];         // (Q+rw_bias) fp16
__device__ __half g_Qrrh[(size_t)BSZ*NH*QLEN*DH];         // (Q+rr_bias) fp16
__device__ __half g_Khb [(size_t)BSZ*NH*KLEN*DH];         // K fp16
__device__ __half g_Vth [(size_t)BSZ*NH*DH*KLEN];         // V^T fp16
__device__ __half g_Rkh [(size_t)NH*KLEN*DH];             // Rk fp16

// ================= helpers =================
__device__ __forceinline__ uint32_t smem_u32(const void* p) {
    uint32_t a;
    asm("{ .reg .u64 t; cvta.to.shared.u64 t, %1; cvt.u32.u64 %0, t; }" : "=r"(a) : "l"(p));
    return a;
}
__device__ __forceinline__ void ldsm4(uint32_t a[4], uint32_t addr) {
    asm volatile("ldmatrix.sync.aligned.m8n8.x4.shared.b16 {%0,%1,%2,%3}, [%4];"
                 : "=r"(a[0]), "=r"(a[1]), "=r"(a[2]), "=r"(a[3]) : "r"(addr));
}
__device__ __forceinline__ void ldsm2(uint32_t b[2], uint32_t addr) {
    asm volatile("ldmatrix.sync.aligned.m8n8.x2.shared.b16 {%0,%1}, [%2];"
                 : "=r"(b[0]), "=r"(b[1]) : "r"(addr));
}
__device__ __forceinline__ void mma16816(float c[4], const uint32_t a[4], const uint32_t b[2]) {
    asm volatile("mma.sync.aligned.m16n8k16.row.col.f32.f16.f16.f32 "
        "{%0,%1,%2,%3}, {%4,%5,%6,%7}, {%8,%9}, {%0,%1,%2,%3};"
        : "+f"(c[0]), "+f"(c[1]), "+f"(c[2]), "+f"(c[3])
        : "r"(a[0]), "r"(a[1]), "r"(a[2]), "r"(a[3]), "r"(b[0]), "r"(b[1]));
}
__device__ __forceinline__ void cpa16(uint32_t dst, const void* src) {
    asm volatile("cp.async.cg.shared.global [%0], [%1], 16;" :: "r"(dst), "l"(src));
}
#define CPA_COMMIT() asm volatile("cp.async.commit_group;")
#define CPA_WAIT1()  asm volatile("cp.async.wait_group 1;")
#define CPA_WAIT2()  asm volatile("cp.async.wait_group 2;")

__device__ __forceinline__ uint32_t f2h2(float a, float b) {
    __half2 t = __floats2half2_rn(a, b);
    return *reinterpret_cast<uint32_t*>(&t);
}
__device__ __forceinline__ uint32_t sphys(int r, int ch) {   // 128B rows, XOR swizzle
    return (uint32_t)(r * 128 + ((ch ^ (r & 7)) << 4));
}

// ---------------- prep kernels ----------------
__global__ __launch_bounds__(256) void round2_k(
    const float* __restrict__ a, const float* __restrict__ b,
    __half* __restrict__ h, int n4each)
{
    int i = blockIdx.x * 256 + threadIdx.x;
    const float* src = (i < n4each) ? a : b;
    int ii = (i < n4each) ? i : i - n4each;
    float4 v = ((const float4*)src)[ii];
    __half hh[4];
    hh[0] = __float2half_rn(v.x); hh[1] = __float2half_rn(v.y);
    hh[2] = __float2half_rn(v.z); hh[3] = __float2half_rn(v.w);
    ((uint2*)h)[i] = *(uint2*)hh;
}

__global__ __launch_bounds__(256) void round_k(
    const float* __restrict__ src, __half* __restrict__ h, int n4)
{
    int i = blockIdx.x * 256 + threadIdx.x;
    if (i >= n4) return;
    float4 v = ((const float4*)src)[i];
    __half hh[4];
    hh[0] = __float2half_rn(v.x); hh[1] = __float2half_rn(v.y);
    hh[2] = __float2half_rn(v.z); hh[3] = __float2half_rn(v.w);
    ((uint2*)h)[i] = *(uint2*)hh;
}

// transpose + round: src [K][N] fp32 -> th [N][K] fp16
__global__ __launch_bounds__(256) void tround_k(
    const float* __restrict__ src, __half* __restrict__ th, int K, int N)
{
    __shared__ float tile[32][33];
    const int n0 = blockIdx.x * 32, k0 = blockIdx.y * 32;
    const int tx = threadIdx.x & 31, ty0 = threadIdx.x >> 5;
#pragma unroll
    for (int it = 0; it < 4; ++it) {
        int ty = ty0 + it * 8;
        tile[ty][tx] = src[(size_t)(k0 + ty) * N + n0 + tx];
    }
    __syncthreads();
#pragma unroll
    for (int it = 0; it < 4; ++it) {
        int ty = ty0 + it * 8;
        th[(size_t)(n0 + ty) * K + k0 + tx] = __float2half_rn(tile[tx][ty]);
    }
}

// per-head V transpose: g_V [bn][j][d] fp32 -> g_Vth [bn][d][j] fp16
__global__ __launch_bounds__(256) void vtrans_k()
{
    __shared__ float tile[64][65];
    const int j0 = blockIdx.x * 64;
    const int bn = blockIdx.y;
    const int tid = threadIdx.x;
#pragma unroll
    for (int it = 0; it < 16; ++it) {
        int idx = tid + it * 256;
        int j = idx >> 6, d = idx & 63;
        tile[j][d] = g_V[((size_t)bn * 1024 + j0 + j) * 64 + d];
    }
    __syncthreads();
#pragma unroll
    for (int it = 0; it < 16; ++it) {
        int idx = tid + it * 256;
        int d = idx >> 6, j = idx & 63;
        g_Vth[((size_t)bn * 64 + d) * 1024 + j0 + j] = __float2half_rn(tile[j][d]);
    }
}

// ---------------- fp16 HMMA GEMM (1 MMA), tile 128x128, BK=64, 3-stage, 2 CTA/SM ----------------
#define GSTG 32768
#define GTC_SMEM (3*GSTG)

template<int MODE>
__global__ __launch_bounds__(256, 2) void gemm_hf(
    const __half* __restrict__ Ah, const __half* __restrict__ Bh,
    float* __restrict__ C, const float* __restrict__ rwb, const float* __restrict__ rrb)
{
    const int m0 = blockIdx.y * 128;
    const int n0 = blockIdx.x * 128;
    if (MODE == 0 && n0 < 1024 && m0 < 8192) return;   // Q of mems: dead

    extern __shared__ char sm[];
    const int tid  = threadIdx.x;
    const int wid  = tid >> 5;
    const int lane = tid & 31;
    const int wm   = wid >> 2;
    const int wn   = wid & 3;
    const uint32_t smb = smem_u32(sm);

    float acc[4][4][4];
#pragma unroll
    for (int i = 0; i < 4; i++)
#pragma unroll
        for (int j = 0; j < 4; j++)
#pragma unroll
            for (int q = 0; q < 4; q++) acc[i][j][q] = 0.f;

    const int lr = tid >> 3;
    const int lc = tid & 7;

    auto load_stage = [&](int c, int stg) {
        const int k0 = c * 64;
        const uint32_t base = smb + stg * GSTG;
#pragma unroll
        for (int it = 0; it < 4; ++it) {
            int r = lr + it * 32;
            uint32_t dst = base + sphys(r, lc);
            cpa16(dst,         Ah + (size_t)(m0 + r) * 1024 + k0 + lc * 8);
            cpa16(dst + 16384, Bh + (size_t)(n0 + r) * 1024 + k0 + lc * 8);
        }
        CPA_COMMIT();
    };

    auto compute = [&](int stg) {
        const uint32_t base = smb + stg * GSTG;
#pragma unroll
        for (int s = 0; s < 4; ++s) {
            uint32_t ah[4][4], bh[4][2];
#pragma unroll
            for (int i = 0; i < 4; ++i) {
                int row = wm * 64 + i * 16 + (lane & 15);
                int ch  = s * 2 + (lane >> 4);
                ldsm4(ah[i], base + sphys(row, ch));
            }
#pragma unroll
            for (int j = 0; j < 4; ++j) {
                int row = wn * 32 + j * 8 + (lane & 7);
                int ch  = s * 2 + ((lane >> 3) & 1);
                ldsm2(bh[j], base + 16384u + sphys(row, ch));
            }
#pragma unroll
            for (int i = 0; i < 4; ++i)
#pragma unroll
                for (int j = 0; j < 4; ++j)
                    mma16816(acc[i][j], ah[i], bh[j]);
        }
    };

    load_stage(0, 0);
    load_stage(1, 1);
    load_stage(2, 2);
    int stg = 0;
#pragma unroll 1
    for (int c = 0; c < 16; ++c) {
        CPA_WAIT2();
        __syncthreads();
        compute(stg);
        __syncthreads();
        if (c + 3 < 16) load_stage(c + 3, stg);
        else            CPA_COMMIT();
        if (++stg == 3) stg = 0;
    }

    const int g   = lane >> 2;
    const int tig = lane & 3;

    auto storeC = [&](int m, int col, float v0, float v1) {
        if (MODE == 0) {
            int kl = m >> 4, bb = m & 15;
            int sec = col >> 10, hn = (col >> 6) & 15, d = col & 63;
            if (sec == 0) {
                if (kl >= MLEN) {
                    size_t o = ((size_t)(bb*NH+hn)*QLEN + (kl-MLEN))*DH + d;
                    float b0 = rwb[hn*64 + d], b1 = rwb[hn*64 + d + 1];
                    *(uint32_t*)&g_Qrwh[o] = f2h2(v0 + b0, v1 + b1);
                    float c0 = rrb[hn*64 + d], c1 = rrb[hn*64 + d + 1];
                    *(uint32_t*)&g_Qrrh[o] = f2h2(v0 + c0, v1 + c1);
                }
            } else if (sec == 1) {
                size_t o = ((size_t)(bb*NH+hn)*KLEN + kl)*DH + d;
                *(uint32_t*)&g_Khb[o] = f2h2(v0, v1);
            } else {
                *(float2*)&g_V[((size_t)(bb*NH+hn)*KLEN + kl)*DH + d] = make_float2(v0, v1);
            }
        } else if (MODE == 1) {
            int hn = col >> 6, d = col & 63;
            *(uint32_t*)&g_Rkh[((size_t)hn*KLEN + m)*DH + d] = f2h2(v0, v1);
        } else {
            *(float2*)&C[(size_t)m * 1024 + col] = make_float2(v0, v1);
        }
    };

#pragma unroll
    for (int i = 0; i < 4; ++i)
#pragma unroll
        for (int j = 0; j < 4; ++j) {
            int m   = m0 + wm*64 + i*16 + g;
            int col = n0 + wn*32 + j*8 + 2*tig;
            storeC(m,     col, acc[i][j][0], acc[i][j][1]);
            storeC(m + 8, col, acc[i][j][2], acc[i][j][3]);
        }
}

// ---------------- BD via HMMA (1 MMA): BD[i][u] = (q+rrb)·rk, 3 CTA/SM ----------------
// smem: Q 8K | stage s (2x): Rk 8K  => 24K
#define BD_SMEM 24576
__global__ __launch_bounds__(128, 3) void bd_mma()
{
    extern __shared__ char sm[];
    const int i0 = blockIdx.x * 64;
    const int bn = blockIdx.y;
    const int nh = bn & 15;
    const int tid = threadIdx.x, wid = tid >> 5, lane = tid & 31;
    const uint32_t smb = smem_u32(sm);

    const int us = (448 - i0) > 0 ? (448 - i0) : 0;
    const int nt = (1024 - us) >> 6;

    const __half* Qh = g_Qrrh + ((size_t)bn*512 + i0) * 64;

#pragma unroll
    for (int it = 0; it < 4; ++it) {
        int idx = tid + it * 128;
        int r = idx >> 3, ch = idx & 7;
        cpa16(smb + sphys(r, ch), Qh + r*64 + ch*8);
    }
    CPA_COMMIT();

    auto load_rk = [&](int t) {
        if (t < nt) {
            int u0 = us + t * 64;
            uint32_t base = smb + 8192 + (t & 1) * 8192;
#pragma unroll
            for (int it = 0; it < 4; ++it) {
                int idx = tid + it * 128;
                int r = idx >> 3, ch = idx & 7;
                cpa16(base + sphys(r, ch), g_Rkh + ((size_t)nh*1024 + u0 + r)*64 + ch*8);
            }
        }
        CPA_COMMIT();
    };
    load_rk(0);
    load_rk(1);

    uint32_t aq[4][4];
    bool afrag = false;

    const int g = lane >> 2, tig = lane & 3;
    const int r0 = i0 + wid * 16 + g;

#pragma unroll 1
    for (int t = 0; t < nt; ++t) {
        CPA_WAIT1();
        __syncthreads();
        if (!afrag) {
            afrag = true;
#pragma unroll
            for (int kc = 0; kc < 4; ++kc) {
                int row = wid * 16 + (lane & 15);
                int ch  = kc * 2 + (lane >> 4);
                ldsm4(aq[kc], smb + sphys(row, ch));
            }
        }
        const uint32_t base = smb + 8192 + (t & 1) * 8192;
        const int u0 = us + t * 64;
        __half* bd0 = g_BDh + ((size_t)bn*512 + r0) * 1024 + u0;
        __half* bd1 = bd0 + 8 * 1024;

#pragma unroll
        for (int jt = 0; jt < 8; ++jt) {
            float sa[4] = {0.f, 0.f, 0.f, 0.f};
            uint32_t kh[4][2], tmp[4];
#pragma unroll
            for (int kp = 0; kp < 2; ++kp) {
                int row = jt * 8 + (lane & 7);
                int ch  = kp * 4 + (lane >> 3);
                ldsm4(tmp, base + sphys(row, ch));
                kh[kp*2][0] = tmp[0]; kh[kp*2][1] = tmp[1];
                kh[kp*2+1][0] = tmp[2]; kh[kp*2+1][1] = tmp[3];
            }
#pragma unroll
            for (int kc = 0; kc < 4; ++kc)
                mma16816(sa, aq[kc], kh[kc]);
            int uc = jt * 8 + 2 * tig;
            *(__half2*)(bd0 + uc) = __floats2half2_rn(sa[0], sa[1]);
            *(__half2*)(bd1 + uc) = __floats2half2_rn(sa[2], sa[3]);
        }
        __syncthreads();
        load_rk(t + 2);
    }
}

// ---------------- fused attention via HMMA + online softmax, 3 CTA/SM ----------------
// smem: Q 8K | stage s (2x): K 8K | V 8K  => 40K
#define ATT_SMEM 40960
__global__ __launch_bounds__(128, 3) void attn_mma()
{
    extern __shared__ char sm[];
    const int i0 = blockIdx.x * 64;
    const int bn = blockIdx.y;
    const int b = bn >> 4, nh = bn & 15;
    const int tid = threadIdx.x, wid = tid >> 5, lane = tid & 31;
    const uint32_t smb = smem_u32(sm);

    const int nt = (i0 >> 6) + 9;

    const __half* Qh = g_Qrwh + ((size_t)bn*512 + i0) * 64;

#pragma unroll
    for (int it = 0; it < 4; ++it) {
        int idx = tid + it * 128;
        int r = idx >> 3, ch = idx & 7;
        cpa16(smb + sphys(r, ch), Qh + r*64 + ch*8);
    }

    auto load_kv = [&](int t) {
        if (t < nt) {
            int j0 = t * 64;
            uint32_t base = smb + 8192 + (t & 1) * 16384;
#pragma unroll
            for (int it = 0; it < 4; ++it) {
                int idx = tid + it * 128;
                int r = idx >> 3, ch = idx & 7;
                cpa16(base + sphys(r, ch),        g_Khb + ((size_t)bn*1024 + j0 + r) * 64 + ch*8);
                cpa16(base + 8192 + sphys(r, ch), g_Vth + ((size_t)bn*64 + r) * 1024 + j0 + ch*8);
            }
        }
        CPA_COMMIT();
    };
    load_kv(0);   // commits Q + KV0 together
    load_kv(1);

    uint32_t aq[4][4];
    bool afrag = false;

    const int g = lane >> 2, tig = lane & 3;
    const int r0 = i0 + wid * 16 + g;
    const int r1 = r0 + 8;
    const __half* bd0 = g_BDh + ((size_t)bn*512 + r0) * 1024;
    const __half* bd1 = bd0 + 8 * 1024;

    float mi0 = -1e30f, mi1 = -1e30f, li0 = 0.f, li1 = 0.f;
    float oacc[8][4];
#pragma unroll
    for (int dt = 0; dt < 8; ++dt)
#pragma unroll
        for (int q = 0; q < 4; ++q) oacc[dt][q] = 0.f;

#pragma unroll 1
    for (int t = 0; t < nt; ++t) {
        CPA_WAIT1();
        __syncthreads();
        if (!afrag) {
            afrag = true;
#pragma unroll
            for (int kc = 0; kc < 4; ++kc) {
                int row = wid * 16 + (lane & 15);
                int ch  = kc * 2 + (lane >> 4);
                ldsm4(aq[kc], smb + sphys(row, ch));
            }
        }
        const uint32_t kbase = smb + 8192 + (t & 1) * 16384;
        const int j0 = t * 64;

        // ---- S = Q·K^T (1 MMA) ----
        float sa[8][4];
#pragma unroll
        for (int jt = 0; jt < 8; ++jt) {
            sa[jt][0] = sa[jt][1] = sa[jt][2] = sa[jt][3] = 0.f;
            uint32_t kh[4][2], tmp[4];
#pragma unroll
            for (int kp = 0; kp < 2; ++kp) {
                int row = jt * 8 + (lane & 7);
                int ch  = kp * 4 + (lane >> 3);
                ldsm4(tmp, kbase + sphys(row, ch));
                kh[kp*2][0] = tmp[0]; kh[kp*2][1] = tmp[1];
                kh[kp*2+1][0] = tmp[2]; kh[kp*2+1][1] = tmp[3];
            }
#pragma unroll
            for (int kc = 0; kc < 4; ++kc)
                mma16816(sa[jt], aq[kc], kh[kc]);
        }

        // ---- + BD, scale, mask ----
#pragma unroll
        for (int jt = 0; jt < 8; ++jt) {
            int j = j0 + jt * 8 + 2 * tig;
            sa[jt][0] = (j     <= r0 + 512) ? (sa[jt][0] + __half2float(bd0[j + 511 - r0])) * 0.125f : -1e30f;
            sa[jt][1] = (j + 1 <= r0 + 512) ? (sa[jt][1] + __half2float(bd0[j + 512 - r0])) * 0.125f : -1e30f;
            sa[jt][2] = (j     <= r1 + 512) ? (sa[jt][2] + __half2float(bd1[j + 511 - r1])) * 0.125f : -1e30f;
            sa[jt][3] = (j + 1 <= r1 + 512) ? (sa[jt][3] + __half2float(bd1[j + 512 - r1])) * 0.125f : -1e30f;
        }

        // ---- online softmax ----
        float m0 = -1e30f, m1 = -1e30f;
#pragma unroll
        for (int jt = 0; jt < 8; ++jt) {
            m0 = fmaxf(m0, fmaxf(sa[jt][0], sa[jt][1]));
            m1 = fmaxf(m1, fmaxf(sa[jt][2], sa[jt][3]));
        }
        m0 = fmaxf(m0, __shfl_xor_sync(0xffffffffu, m0, 1));
        m0 = fmaxf(m0, __shfl_xor_sync(0xffffffffu, m0, 2));
        m1 = fmaxf(m1, __shfl_xor_sync(0xffffffffu, m1, 1));
        m1 = fmaxf(m1, __shfl_xor_sync(0xffffffffu, m1, 2));
        float mn0 = fmaxf(mi0, m0), mn1 = fmaxf(mi1, m1);
        float al0 = __expf(mi0 - mn0), al1 = __expf(mi1 - mn1);
        mi0 = mn0; mi1 = mn1;
        float s0 = 0.f, s1 = 0.f;
#pragma unroll
        for (int jt = 0; jt < 8; ++jt) {
            sa[jt][0] = __expf(sa[jt][0] - mn0); s0 += sa[jt][0];
            sa[jt][1] = __expf(sa[jt][1] - mn0); s0 += sa[jt][1];
            sa[jt][2] = __expf(sa[jt][2] - mn1); s1 += sa[jt][2];
            sa[jt][3] = __expf(sa[jt][3] - mn1); s1 += sa[jt][3];
        }
        s0 += __shfl_xor_sync(0xffffffffu, s0, 1);
        s0 += __shfl_xor_sync(0xffffffffu, s0, 2);
        s1 += __shfl_xor_sync(0xffffffffu, s1, 1);
        s1 += __shfl_xor_sync(0xffffffffu, s1, 2);
        li0 = li0 * al0 + s0;
        li1 = li1 * al1 + s1;
#pragma unroll
        for (int dt = 0; dt < 8; ++dt) {
            oacc[dt][0] *= al0; oacc[dt][1] *= al0;
            oacc[dt][2] *= al1; oacc[dt][3] *= al1;
        }

        // ---- pack P (fp16) ----
        uint32_t pf[4][4];
#pragma unroll
        for (int kc = 0; kc < 4; ++kc) {
            pf[kc][0] = f2h2(sa[2*kc][0],   sa[2*kc][1]);
            pf[kc][1] = f2h2(sa[2*kc][2],   sa[2*kc][3]);
            pf[kc][2] = f2h2(sa[2*kc+1][0], sa[2*kc+1][1]);
            pf[kc][3] = f2h2(sa[2*kc+1][2], sa[2*kc+1][3]);
        }

        // ---- O += P · V (1 MMA) ----
        const uint32_t vbase = kbase + 8192;
#pragma unroll
        for (int dt = 0; dt < 8; ++dt) {
            uint32_t vh[4][2], tmp[4];
#pragma unroll
            for (int kp = 0; kp < 2; ++kp) {
                int row = dt * 8 + (lane & 7);
                int ch  = kp * 4 + (lane >> 3);
                ldsm4(tmp, vbase + sphys(row, ch));
                vh[kp*2][0] = tmp[0]; vh[kp*2][1] = tmp[1];
                vh[kp*2+1][0] = tmp[2]; vh[kp*2+1][1] = tmp[3];
            }
#pragma unroll
            for (int kc = 0; kc < 4; ++kc)
                mma16816(oacc[dt], pf[kc], vh[kc]);
        }
        __syncthreads();
        load_kv(t + 2);
    }

    // ---- store AV as fp16 ----
    float inv0 = 1.f / li0, inv1 = 1.f / li1;
#pragma unroll
    for (int dt = 0; dt < 8; ++dt) {
        int d = nh * 64 + dt * 8 + 2 * tig;
        *(uint32_t*)&g_AVh[((size_t)r0 * 16 + b) * 1024 + d] =
            f2h2(oacc[dt][0] * inv0, oacc[dt][1] * inv0);
        *(uint32_t*)&g_AVh[((size_t)r1 * 16 + b) * 1024 + d] =
            f2h2(oacc[dt][2] * inv1, oacc[dt][3] * inv1);
    }
}

// ---------------- residual + layernorm (warp-shuffle reductions) ----------------
__global__ __launch_bounds__(256) void ln_kernel(
    const float* __restrict__ w, const float* __restrict__ gamma,
    const float* __restrict__ beta, float* __restrict__ out)
{
    const int row = blockIdx.x;
    const int tid = threadIdx.x;
    const int lane = tid & 31, wid = tid >> 5;
    __shared__ float wred[8];
    const float* wrow = w   + (size_t)row * 1024;
    float*       orow = out + (size_t)row * 1024;

    float x[4];
    float sum = 0.f;
#pragma unroll
    for (int l = 0; l < 4; l++) {
        int c = tid + l*256;
        x[l] = wrow[c] + orow[c];
        sum += x[l];
    }
#pragma unroll
    for (int off = 16; off; off >>= 1) sum += __shfl_xor_sync(0xffffffffu, sum, off);
    if (lane == 0) wred[wid] = sum;
    __syncthreads();
    float tot = 0.f;
#pragma unroll
    for (int q = 0; q < 8; ++q) tot += wred[q];
    float mu = tot * (1.f/1024.f);
    __syncthreads();

    float vs = 0.f;
#pragma unroll
    for (int l = 0; l < 4; l++) { float dx = x[l] - mu; vs += dx*dx; }
#pragma unroll
    for (int off = 16; off; off >>= 1) vs += __shfl_xor_sync(0xffffffffu, vs, off);
    if (lane == 0) wred[wid] = vs;
    __syncthreads();
    float vtot = 0.f;
#pragma unroll
    for (int q = 0; q < 8; ++q) vtot += wred[q];
    float rstd = rsqrtf(vtot * (1.f/1024.f) + 1e-6f);

#pragma unroll
    for (int l = 0; l < 4; l++) {
        int c = tid + l*256;
        orow[c] = (x[l] - mu) * rstd * gamma[c] + beta[c];
    }
}

// ---------------- launch ----------------
extern "C" void kernel_launch(void* const* d_in, const int* in_sizes, int n_in,
                              void* d_out, int out_size)
{
    const float* w      = (const float*)d_in[0];
    const float* r      = (const float*)d_in[1];
    const float* mems   = (const float*)d_in[3];
    const float* qkvw   = (const float*)d_in[4];
    const float* rw     = (const float*)d_in[5];
    const float* ow     = (const float*)d_in[6];
    const float* rrb    = (const float*)d_in[7];
    const float* rwbias = (const float*)d_in[8];
    const float* gamma  = (const float*)d_in[9];
    const float* beta   = (const float*)d_in[10];
    float* out = (float*)d_out;

    __half *Ah, *Wth, *R2h, *RWth, *OWth, *AVh;
    cudaGetSymbolAddress((void**)&Ah,  g_Ah);
    cudaGetSymbolAddress((void**)&Wth, g_Wth);
    cudaGetSymbolAddress((void**)&R2h, g_R2h);
    cudaGetSymbolAddress((void**)&RWth,g_RWth);
    cudaGetSymbolAddress((void**)&OWth,g_OWth);
    cudaGetSymbolAddress((void**)&AVh, g_AVh);

    cudaFuncSetAttribute(gemm_hf<0>, cudaFuncAttributeMaxDynamicSharedMemorySize, GTC_SMEM);
    cudaFuncSetAttribute(gemm_hf<1>, cudaFuncAttributeMaxDynamicSharedMemorySize, GTC_SMEM);
    cudaFuncSetAttribute(gemm_hf<2>, cudaFuncAttributeMaxDynamicSharedMemorySize, GTC_SMEM);
    cudaFuncSetAttribute(bd_mma,   cudaFuncAttributeMaxDynamicSharedMemorySize, BD_SMEM);
    cudaFuncSetAttribute(attn_mma, cudaFuncAttributeMaxDynamicSharedMemorySize, ATT_SMEM);

    // prep
    round2_k<<<16384, 256>>>(mems, w, Ah, 2097152);
    tround_k<<<dim3(96, 32), 256>>>(qkvw, Wth, 1024, 3072);
    round_k <<<1024, 256>>>(r, R2h, 262144);
    tround_k<<<dim3(32, 32), 256>>>(rw, RWth, 1024, 1024);
    tround_k<<<dim3(32, 32), 256>>>(ow, OWth, 1024, 1024);

    // GEMMs (epilogues write attention operands directly)
    gemm_hf<0><<<dim3(24, 128), 256, GTC_SMEM>>>(Ah, Wth, nullptr, rwbias, rrb);
    gemm_hf<1><<<dim3(8, 8),    256, GTC_SMEM>>>(R2h, RWth, nullptr, nullptr, nullptr);
    vtrans_k<<<dim3(16, 256), 256>>>();

    // BD + attention
    bd_mma  <<<dim3(8, 256), 128, BD_SMEM>>>();
    attn_mma<<<dim3(8, 256), 128, ATT_SMEM>>>();

    // output projection + layernorm
    gemm_hf<2><<<dim3(8, 64),   256, GTC_SMEM>>>(AVh, OWth, out, nullptr, nullptr);
    ln_kernel  <<<8192, 256>>>(w, gamma, beta, out);
}

// round 14
// speedup vs baseline: 1.3462x; 1.0208x over previous
#include <cuda_runtime.h>
#include <cuda_fp16.h>
#include <math.h>
#include <stdint.h>

#define QLEN 512
#define MLEN 512
#define KLEN 1024
#define BSZ  16
#define NH   16
#define DH   64
#define DM   1024
#define HID  1024

// ---------------- scratch ----------------
__device__ float  g_V  [(size_t)BSZ*NH*KLEN*DH];          // fp32 V (for transpose)
__device__ __half g_BDh[(size_t)BSZ*NH*QLEN*KLEN];        // BD scores fp16

__device__ __half g_Ah [(size_t)16384*1024];              // cat(mems,w) fp16
__device__ __half g_Wth[(size_t)3072*1024];               // qkv_w^T fp16
__device__ __half g_R2h[(size_t)1024*1024];               // r fp16
__device__ __half g_RWth[(size_t)1024*1024];              // r_w^T fp16
__device__ __half g_OWth[(size_t)1024*1024];              // o_w^T fp16
__device__ __half g_AVh[(size_t)8192*1024];               // attn_vec fp16

__device__ __half g_Qrwh[(size_t)BSZ*NH*QLEN*DH];         // (Q+rw_bias) fp16
__device__ __half g_Qrrh[(size_t)BSZ*NH*QLEN*DH];         // (Q+rr_bias) fp16
__device__ __half g_Khb [(size_t)BSZ*NH*KLEN*DH];         // K fp16
__device__ __half g_Vth [(size_t)BSZ*NH*DH*KLEN];         // V^T fp16
__device__ __half g_Rkh [(size_t)NH*KLEN*DH];             // Rk fp16

// ================= helpers =================
__device__ __forceinline__ uint32_t smem_u32(const void* p) {
    uint32_t a;
    asm("{ .reg .u64 t; cvta.to.shared.u64 t, %1; cvt.u32.u64 %0, t; }" : "=r"(a) : "l"(p));
    return a;
}
__device__ __forceinline__ void ldsm4(uint32_t a[4], uint32_t addr) {
    asm volatile("ldmatrix.sync.aligned.m8n8.x4.shared.b16 {%0,%1,%2,%3}, [%4];"
                 : "=r"(a[0]), "=r"(a[1]), "=r"(a[2]), "=r"(a[3]) : "r"(addr));
}
__device__ __forceinline__ void ldsm2(uint32_t b[2], uint32_t addr) {
    asm volatile("ldmatrix.sync.aligned.m8n8.x2.shared.b16 {%0,%1}, [%2];"
                 : "=r"(b[0]), "=r"(b[1]) : "r"(addr));
}
__device__ __forceinline__ void mma16816(float c[4], const uint32_t a[4], const uint32_t b[2]) {
    asm volatile("mma.sync.aligned.m16n8k16.row.col.f32.f16.f16.f32 "
        "{%0,%1,%2,%3}, {%4,%5,%6,%7}, {%8,%9}, {%0,%1,%2,%3};"
        : "+f"(c[0]), "+f"(c[1]), "+f"(c[2]), "+f"(c[3])
        : "r"(a[0]), "r"(a[1]), "r"(a[2]), "r"(a[3]), "r"(b[0]), "r"(b[1]));
}
__device__ __forceinline__ void cpa16(uint32_t dst, const void* src) {
    asm volatile("cp.async.cg.shared.global [%0], [%1], 16;" :: "r"(dst), "l"(src));
}
#define CPA_COMMIT() asm volatile("cp.async.commit_group;")
#define CPA_WAIT1()  asm volatile("cp.async.wait_group 1;")
#define CPA_WAIT2()  asm volatile("cp.async.wait_group 2;")

__device__ __forceinline__ uint32_t f2h2(float a, float b) {
    __half2 t = __floats2half2_rn(a, b);
    return *reinterpret_cast<uint32_t*>(&t);
}
__device__ __forceinline__ uint32_t sphys(int r, int ch) {   // 128B rows, XOR swizzle
    return (uint32_t)(r * 128 + ((ch ^ (r & 7)) << 4));
}

// ---------------- prep kernels ----------------
__global__ __launch_bounds__(256) void round2_k(
    const float* __restrict__ a, const float* __restrict__ b,
    __half* __restrict__ h, int n4each)
{
    int i = blockIdx.x * 256 + threadIdx.x;
    const float* src = (i < n4each) ? a : b;
    int ii = (i < n4each) ? i : i - n4each;
    float4 v = ((const float4*)src)[ii];
    __half hh[4];
    hh[0] = __float2half_rn(v.x); hh[1] = __float2half_rn(v.y);
    hh[2] = __float2half_rn(v.z); hh[3] = __float2half_rn(v.w);
    ((uint2*)h)[i] = *(uint2*)hh;
}

__global__ __launch_bounds__(256) void round_k(
    const float* __restrict__ src, __half* __restrict__ h, int n4)
{
    int i = blockIdx.x * 256 + threadIdx.x;
    if (i >= n4) return;
    float4 v = ((const float4*)src)[i];
    __half hh[4];
    hh[0] = __float2half_rn(v.x); hh[1] = __float2half_rn(v.y);
    hh[2] = __float2half_rn(v.z); hh[3] = __float2half_rn(v.w);
    ((uint2*)h)[i] = *(uint2*)hh;
}

// transpose + round: src [K][N] fp32 -> th [N][K] fp16
__global__ __launch_bounds__(256) void tround_k(
    const float* __restrict__ src, __half* __restrict__ th, int K, int N)
{
    __shared__ float tile[32][33];
    const int n0 = blockIdx.x * 32, k0 = blockIdx.y * 32;
    const int tx = threadIdx.x & 31, ty0 = threadIdx.x >> 5;
#pragma unroll
    for (int it = 0; it < 4; ++it) {
        int ty = ty0 + it * 8;
        tile[ty][tx] = src[(size_t)(k0 + ty) * N + n0 + tx];
    }
    __syncthreads();
#pragma unroll
    for (int it = 0; it < 4; ++it) {
        int ty = ty0 + it * 8;
        th[(size_t)(n0 + ty) * K + k0 + tx] = __float2half_rn(tile[tx][ty]);
    }
}

// per-head V transpose: g_V [bn][j][d] fp32 -> g_Vth [bn][d][j] fp16
__global__ __launch_bounds__(256) void vtrans_k()
{
    __shared__ float tile[64][65];
    const int j0 = blockIdx.x * 64;
    const int bn = blockIdx.y;
    const int tid = threadIdx.x;
#pragma unroll
    for (int it = 0; it < 16; ++it) {
        int idx = tid + it * 256;
        int j = idx >> 6, d = idx & 63;
        tile[j][d] = g_V[((size_t)bn * 1024 + j0 + j) * 64 + d];
    }
    __syncthreads();
#pragma unroll
    for (int it = 0; it < 16; ++it) {
        int idx = tid + it * 256;
        int d = idx >> 6, j = idx & 63;
        g_Vth[((size_t)bn * 64 + d) * 1024 + j0 + j] = __float2half_rn(tile[j][d]);
    }
}

// ---------------- fp16 HMMA GEMM (1 MMA), tile 128x128, BK=64, 3-stage, 2 CTA/SM ----------------
#define GSTG 32768
#define GTC_SMEM (3*GSTG)

template<int MODE>
__global__ __launch_bounds__(256, 2) void gemm_hf(
    const __half* __restrict__ Ah, const __half* __restrict__ Bh,
    float* __restrict__ C, const float* __restrict__ rwb, const float* __restrict__ rrb)
{
    const int m0 = blockIdx.y * 128;
    const int n0 = blockIdx.x * 128;
    if (MODE == 0 && n0 < 1024 && m0 < 8192) return;   // Q of mems: dead

    extern __shared__ char sm[];
    const int tid  = threadIdx.x;
    const int wid  = tid >> 5;
    const int lane = tid & 31;
    const int wm   = wid >> 2;
    const int wn   = wid & 3;
    const uint32_t smb = smem_u32(sm);

    float acc[4][4][4];
#pragma unroll
    for (int i = 0; i < 4; i++)
#pragma unroll
        for (int j = 0; j < 4; j++)
#pragma unroll
            for (int q = 0; q < 4; q++) acc[i][j][q] = 0.f;

    const int lr = tid >> 3;
    const int lc = tid & 7;

    auto load_stage = [&](int c, int stg) {
        const int k0 = c * 64;
        const uint32_t base = smb + stg * GSTG;
#pragma unroll
        for (int it = 0; it < 4; ++it) {
            int r = lr + it * 32;
            uint32_t dst = base + sphys(r, lc);
            cpa16(dst,         Ah + (size_t)(m0 + r) * 1024 + k0 + lc * 8);
            cpa16(dst + 16384, Bh + (size_t)(n0 + r) * 1024 + k0 + lc * 8);
        }
        CPA_COMMIT();
    };

    auto compute = [&](int stg) {
        const uint32_t base = smb + stg * GSTG;
#pragma unroll
        for (int s = 0; s < 4; ++s) {
            uint32_t ah[4][4], bh[4][2];
#pragma unroll
            for (int i = 0; i < 4; ++i) {
                int row = wm * 64 + i * 16 + (lane & 15);
                int ch  = s * 2 + (lane >> 4);
                ldsm4(ah[i], base + sphys(row, ch));
            }
#pragma unroll
            for (int j = 0; j < 4; ++j) {
                int row = wn * 32 + j * 8 + (lane & 7);
                int ch  = s * 2 + ((lane >> 3) & 1);
                ldsm2(bh[j], base + 16384u + sphys(row, ch));
            }
#pragma unroll
            for (int i = 0; i < 4; ++i)
#pragma unroll
                for (int j = 0; j < 4; ++j)
                    mma16816(acc[i][j], ah[i], bh[j]);
        }
    };

    load_stage(0, 0);
    load_stage(1, 1);
    load_stage(2, 2);
    int stg = 0;
#pragma unroll 1
    for (int c = 0; c < 16; ++c) {
        CPA_WAIT2();
        __syncthreads();
        compute(stg);
        __syncthreads();
        if (c + 3 < 16) load_stage(c + 3, stg);
        else            CPA_COMMIT();
        if (++stg == 3) stg = 0;
    }

    const int g   = lane >> 2;
    const int tig = lane & 3;

    auto storeC = [&](int m, int col, float v0, float v1) {
        if (MODE == 0) {
            int kl = m >> 4, bb = m & 15;
            int sec = col >> 10, hn = (col >> 6) & 15, d = col & 63;
            if (sec == 0) {
                if (kl >= MLEN) {
                    size_t o = ((size_t)(bb*NH+hn)*QLEN + (kl-MLEN))*DH + d;
                    float b0 = rwb[hn*64 + d], b1 = rwb[hn*64 + d + 1];
                    *(uint32_t*)&g_Qrwh[o] = f2h2(v0 + b0, v1 + b1);
                    float c0 = rrb[hn*64 + d], c1 = rrb[hn*64 + d + 1];
                    *(uint32_t*)&g_Qrrh[o] = f2h2(v0 + c0, v1 + c1);
                }
            } else if (sec == 1) {
                size_t o = ((size_t)(bb*NH+hn)*KLEN + kl)*DH + d;
                *(uint32_t*)&g_Khb[o] = f2h2(v0, v1);
            } else {
                *(float2*)&g_V[((size_t)(bb*NH+hn)*KLEN + kl)*DH + d] = make_float2(v0, v1);
            }
        } else if (MODE == 1) {
            int hn = col >> 6, d = col & 63;
            *(uint32_t*)&g_Rkh[((size_t)hn*KLEN + m)*DH + d] = f2h2(v0, v1);
        } else {
            *(float2*)&C[(size_t)m * 1024 + col] = make_float2(v0, v1);
        }
    };

#pragma unroll
    for (int i = 0; i < 4; ++i)
#pragma unroll
        for (int j = 0; j < 4; ++j) {
            int m   = m0 + wm*64 + i*16 + g;
            int col = n0 + wn*32 + j*8 + 2*tig;
            storeC(m,     col, acc[i][j][0], acc[i][j][1]);
            storeC(m + 8, col, acc[i][j][2], acc[i][j][3]);
        }
}

// ---------------- BD via HMMA: i-tile 128 (2 row-groups/warp), 3 CTA/SM ----------------
// smem: Q 16K | stage s (2x): Rk 8K  => 32K
#define BD_SMEM 32768
__global__ __launch_bounds__(128, 3) void bd_mma()
{
    extern __shared__ char sm[];
    const int i0 = ((int)gridDim.x - 1 - (int)blockIdx.x) * 128;   // heavy tiles first
    const int bn = blockIdx.y;
    const int nh = bn & 15;
    const int tid = threadIdx.x, wid = tid >> 5, lane = tid & 31;
    const uint32_t smb = smem_u32(sm);

    const int us = (384 - i0) > 0 ? (384 - i0) : 0;   // min u read by any row in tile
    const int nt = (1024 - us) >> 6;

    const __half* Qh = g_Qrrh + ((size_t)bn*512 + i0) * 64;

#pragma unroll
    for (int it = 0; it < 8; ++it) {
        int idx = tid + it * 128;
        int r = idx >> 3, ch = idx & 7;
        cpa16(smb + sphys(r, ch), Qh + r*64 + ch*8);
    }
    CPA_COMMIT();

    auto load_rk = [&](int t) {
        if (t < nt) {
            int u0 = us + t * 64;
            uint32_t base = smb + 16384 + (t & 1) * 8192;
#pragma unroll
            for (int it = 0; it < 4; ++it) {
                int idx = tid + it * 128;
                int r = idx >> 3, ch = idx & 7;
                cpa16(base + sphys(r, ch), g_Rkh + ((size_t)nh*1024 + u0 + r)*64 + ch*8);
            }
        }
        CPA_COMMIT();
    };
    load_rk(0);
    load_rk(1);

    uint32_t aq[2][4][4];
    bool afrag = false;

    const int g = lane >> 2, tig = lane & 3;
    const int rb0 = i0 + wid * 32 + g;          // rg0 rows rb0, rb0+8
    const int rb1 = rb0 + 16;                   // rg1 rows rb1, rb1+8

#pragma unroll 1
    for (int t = 0; t < nt; ++t) {
        CPA_WAIT1();
        __syncthreads();
        if (!afrag) {
            afrag = true;
#pragma unroll
            for (int rg = 0; rg < 2; ++rg)
#pragma unroll
                for (int kc = 0; kc < 4; ++kc) {
                    int row = wid * 32 + rg * 16 + (lane & 15);
                    int ch  = kc * 2 + (lane >> 4);
                    ldsm4(aq[rg][kc], smb + sphys(row, ch));
                }
        }
        const uint32_t base = smb + 16384 + (t & 1) * 8192;
        const int u0 = us + t * 64;
        __half* o00 = g_BDh + ((size_t)bn*512 + rb0) * 1024 + u0;
        __half* o01 = o00 + 8 * 1024;
        __half* o10 = g_BDh + ((size_t)bn*512 + rb1) * 1024 + u0;
        __half* o11 = o10 + 8 * 1024;

#pragma unroll
        for (int jt = 0; jt < 8; ++jt) {
            uint32_t kh[4][2], tmp[4];
#pragma unroll
            for (int kp = 0; kp < 2; ++kp) {
                int row = jt * 8 + (lane & 7);
                int ch  = kp * 4 + (lane >> 3);
                ldsm4(tmp, base + sphys(row, ch));
                kh[kp*2][0] = tmp[0]; kh[kp*2][1] = tmp[1];
                kh[kp*2+1][0] = tmp[2]; kh[kp*2+1][1] = tmp[3];
            }
            float s0[4] = {0.f,0.f,0.f,0.f}, s1[4] = {0.f,0.f,0.f,0.f};
#pragma unroll
            for (int kc = 0; kc < 4; ++kc) {
                mma16816(s0, aq[0][kc], kh[kc]);
                mma16816(s1, aq[1][kc], kh[kc]);
            }
            int uc = jt * 8 + 2 * tig;
            *(__half2*)(o00 + uc) = __floats2half2_rn(s0[0], s0[1]);
            *(__half2*)(o01 + uc) = __floats2half2_rn(s0[2], s0[3]);
            *(__half2*)(o10 + uc) = __floats2half2_rn(s1[0], s1[1]);
            *(__half2*)(o11 + uc) = __floats2half2_rn(s1[2], s1[3]);
        }
        __syncthreads();
        load_rk(t + 2);
    }
}

// ---------------- fused attention: i-tile 128 (2 row-groups/warp), 2 CTA/SM ----------------
// smem: Q 16K | stage s (2x): K 8K | V 8K  => 48K
#define ATT_SMEM 49152
__global__ __launch_bounds__(128, 2) void attn_mma()
{
    extern __shared__ char sm[];
    const int i0 = ((int)gridDim.x - 1 - (int)blockIdx.x) * 128;   // heavy tiles first
    const int bn = blockIdx.y;
    const int b = bn >> 4, nh = bn & 15;
    const int tid = threadIdx.x, wid = tid >> 5, lane = tid & 31;
    const uint32_t smb = smem_u32(sm);

    const int nt = (i0 >> 6) + 10;

    const __half* Qh = g_Qrwh + ((size_t)bn*512 + i0) * 64;

#pragma unroll
    for (int it = 0; it < 8; ++it) {
        int idx = tid + it * 128;
        int r = idx >> 3, ch = idx & 7;
        cpa16(smb + sphys(r, ch), Qh + r*64 + ch*8);
    }

    auto load_kv = [&](int t) {
        if (t < nt) {
            int j0 = t * 64;
            uint32_t base = smb + 16384 + (t & 1) * 16384;
#pragma unroll
            for (int it = 0; it < 4; ++it) {
                int idx = tid + it * 128;
                int r = idx >> 3, ch = idx & 7;
                cpa16(base + sphys(r, ch),        g_Khb + ((size_t)bn*1024 + j0 + r) * 64 + ch*8);
                cpa16(base + 8192 + sphys(r, ch), g_Vth + ((size_t)bn*64 + r) * 1024 + j0 + ch*8);
            }
        }
        CPA_COMMIT();
    };
    load_kv(0);   // commits Q + KV0 together
    load_kv(1);

    uint32_t aq[2][4][4];
    bool afrag = false;

    const int g = lane >> 2, tig = lane & 3;
    const int rb[2] = { i0 + wid * 32 + g, i0 + wid * 32 + 16 + g };
    const __half* bdp[2][2];
#pragma unroll
    for (int rg = 0; rg < 2; ++rg) {
        bdp[rg][0] = g_BDh + ((size_t)bn*512 + rb[rg]) * 1024;
        bdp[rg][1] = bdp[rg][0] + 8 * 1024;
    }

    float mi[2][2], li[2][2];
#pragma unroll
    for (int rg = 0; rg < 2; ++rg) { mi[rg][0] = mi[rg][1] = -1e30f; li[rg][0] = li[rg][1] = 0.f; }
    float oacc[2][8][4];
#pragma unroll
    for (int rg = 0; rg < 2; ++rg)
#pragma unroll
        for (int dt = 0; dt < 8; ++dt)
#pragma unroll
            for (int q = 0; q < 4; ++q) oacc[rg][dt][q] = 0.f;

#pragma unroll 1
    for (int t = 0; t < nt; ++t) {
        CPA_WAIT1();
        __syncthreads();
        if (!afrag) {
            afrag = true;
#pragma unroll
            for (int rg = 0; rg < 2; ++rg)
#pragma unroll
                for (int kc = 0; kc < 4; ++kc) {
                    int row = wid * 32 + rg * 16 + (lane & 15);
                    int ch  = kc * 2 + (lane >> 4);
                    ldsm4(aq[rg][kc], smb + sphys(row, ch));
                }
        }
        const uint32_t kbase = smb + 16384 + (t & 1) * 16384;
        const int j0 = t * 64;

        // ---- S = Q·K^T, shared K fragments across both row-groups ----
        float sa[2][8][4];
#pragma unroll
        for (int jt = 0; jt < 8; ++jt) {
            uint32_t kh[4][2], tmp[4];
#pragma unroll
            for (int kp = 0; kp < 2; ++kp) {
                int row = jt * 8 + (lane & 7);
                int ch  = kp * 4 + (lane >> 3);
                ldsm4(tmp, kbase + sphys(row, ch));
                kh[kp*2][0] = tmp[0]; kh[kp*2][1] = tmp[1];
                kh[kp*2+1][0] = tmp[2]; kh[kp*2+1][1] = tmp[3];
            }
#pragma unroll
            for (int q = 0; q < 4; ++q) { sa[0][jt][q] = 0.f; sa[1][jt][q] = 0.f; }
#pragma unroll
            for (int kc = 0; kc < 4; ++kc) {
                mma16816(sa[0][jt], aq[0][kc], kh[kc]);
                mma16816(sa[1][jt], aq[1][kc], kh[kc]);
            }
        }

        // ---- per row-group: BD add/mask, online softmax, pack P ----
        uint32_t pf[2][4][4];
#pragma unroll
        for (int rg = 0; rg < 2; ++rg) {
            const int r0 = rb[rg], r1 = rb[rg] + 8;
            const __half* b0p = bdp[rg][0];
            const __half* b1p = bdp[rg][1];
#pragma unroll
            for (int jt = 0; jt < 8; ++jt) {
                int j = j0 + jt * 8 + 2 * tig;
                sa[rg][jt][0] = (j     <= r0 + 512) ? (sa[rg][jt][0] + __half2float(b0p[j + 511 - r0])) * 0.125f : -1e30f;
                sa[rg][jt][1] = (j + 1 <= r0 + 512) ? (sa[rg][jt][1] + __half2float(b0p[j + 512 - r0])) * 0.125f : -1e30f;
                sa[rg][jt][2] = (j     <= r1 + 512) ? (sa[rg][jt][2] + __half2float(b1p[j + 511 - r1])) * 0.125f : -1e30f;
                sa[rg][jt][3] = (j + 1 <= r1 + 512) ? (sa[rg][jt][3] + __half2float(b1p[j + 512 - r1])) * 0.125f : -1e30f;
            }

            float m0 = -1e30f, m1 = -1e30f;
#pragma unroll
            for (int jt = 0; jt < 8; ++jt) {
                m0 = fmaxf(m0, fmaxf(sa[rg][jt][0], sa[rg][jt][1]));
                m1 = fmaxf(m1, fmaxf(sa[rg][jt][2], sa[rg][jt][3]));
            }
            m0 = fmaxf(m0, __shfl_xor_sync(0xffffffffu, m0, 1));
            m0 = fmaxf(m0, __shfl_xor_sync(0xffffffffu, m0, 2));
            m1 = fmaxf(m1, __shfl_xor_sync(0xffffffffu, m1, 1));
            m1 = fmaxf(m1, __shfl_xor_sync(0xffffffffu, m1, 2));
            float mn0 = fmaxf(mi[rg][0], m0), mn1 = fmaxf(mi[rg][1], m1);
            float al0 = __expf(mi[rg][0] - mn0), al1 = __expf(mi[rg][1] - mn1);
            mi[rg][0] = mn0; mi[rg][1] = mn1;
            float s0 = 0.f, s1 = 0.f;
#pragma unroll
            for (int jt = 0; jt < 8; ++jt) {
                sa[rg][jt][0] = __expf(sa[rg][jt][0] - mn0); s0 += sa[rg][jt][0];
                sa[rg][jt][1] = __expf(sa[rg][jt][1] - mn0); s0 += sa[rg][jt][1];
                sa[rg][jt][2] = __expf(sa[rg][jt][2] - mn1); s1 += sa[rg][jt][2];
                sa[rg][jt][3] = __expf(sa[rg][jt][3] - mn1); s1 += sa[rg][jt][3];
            }
            s0 += __shfl_xor_sync(0xffffffffu, s0, 1);
            s0 += __shfl_xor_sync(0xffffffffu, s0, 2);
            s1 += __shfl_xor_sync(0xffffffffu, s1, 1);
            s1 += __shfl_xor_sync(0xffffffffu, s1, 2);
            li[rg][0] = li[rg][0] * al0 + s0;
            li[rg][1] = li[rg][1] * al1 + s1;
#pragma unroll
            for (int dt = 0; dt < 8; ++dt) {
                oacc[rg][dt][0] *= al0; oacc[rg][dt][1] *= al0;
                oacc[rg][dt][2] *= al1; oacc[rg][dt][3] *= al1;
            }
#pragma unroll
            for (int kc = 0; kc < 4; ++kc) {
                pf[rg][kc][0] = f2h2(sa[rg][2*kc][0],   sa[rg][2*kc][1]);
                pf[rg][kc][1] = f2h2(sa[rg][2*kc][2],   sa[rg][2*kc][3]);
                pf[rg][kc][2] = f2h2(sa[rg][2*kc+1][0], sa[rg][2*kc+1][1]);
                pf[rg][kc][3] = f2h2(sa[rg][2*kc+1][2], sa[rg][2*kc+1][3]);
            }
        }

        // ---- O += P · V, shared V fragments across both row-groups ----
        const uint32_t vbase = kbase + 8192;
#pragma unroll
        for (int dt = 0; dt < 8; ++dt) {
            uint32_t vh[4][2], tmp[4];
#pragma unroll
            for (int kp = 0; kp < 2; ++kp) {
                int row = dt * 8 + (lane & 7);
                int ch  = kp * 4 + (lane >> 3);
                ldsm4(tmp, vbase + sphys(row, ch));
                vh[kp*2][0] = tmp[0]; vh[kp*2][1] = tmp[1];
                vh[kp*2+1][0] = tmp[2]; vh[kp*2+1][1] = tmp[3];
            }
#pragma unroll
            for (int kc = 0; kc < 4; ++kc) {
                mma16816(oacc[0][dt], pf[0][kc], vh[kc]);
                mma16816(oacc[1][dt], pf[1][kc], vh[kc]);
            }
        }
        __syncthreads();
        load_kv(t + 2);
    }

    // ---- store AV as fp16 ----
#pragma unroll
    for (int rg = 0; rg < 2; ++rg) {
        float inv0 = 1.f / li[rg][0], inv1 = 1.f / li[rg][1];
        const int r0 = rb[rg], r1 = rb[rg] + 8;
#pragma unroll
        for (int dt = 0; dt < 8; ++dt) {
            int d = nh * 64 + dt * 8 + 2 * tig;
            *(uint32_t*)&g_AVh[((size_t)r0 * 16 + b) * 1024 + d] =
                f2h2(oacc[rg][dt][0] * inv0, oacc[rg][dt][1] * inv0);
            *(uint32_t*)&g_AVh[((size_t)r1 * 16 + b) * 1024 + d] =
                f2h2(oacc[rg][dt][2] * inv1, oacc[rg][dt][3] * inv1);
        }
    }
}

// ---------------- residual + layernorm (warp-shuffle reductions) ----------------
__global__ __launch_bounds__(256) void ln_kernel(
    const float* __restrict__ w, const float* __restrict__ gamma,
    const float* __restrict__ beta, float* __restrict__ out)
{
    const int row = blockIdx.x;
    const int tid = threadIdx.x;
    const int lane = tid & 31, wid = tid >> 5;
    __shared__ float wred[8];
    const float* wrow = w   + (size_t)row * 1024;
    float*       orow = out + (size_t)row * 1024;

    float x[4];
    float sum = 0.f;
#pragma unroll
    for (int l = 0; l < 4; l++) {
        int c = tid + l*256;
        x[l] = wrow[c] + orow[c];
        sum += x[l];
    }
#pragma unroll
    for (int off = 16; off; off >>= 1) sum += __shfl_xor_sync(0xffffffffu, sum, off);
    if (lane == 0) wred[wid] = sum;
    __syncthreads();
    float tot = 0.f;
#pragma unroll
    for (int q = 0; q < 8; ++q) tot += wred[q];
    float mu = tot * (1.f/1024.f);
    __syncthreads();

    float vs = 0.f;
#pragma unroll
    for (int l = 0; l < 4; l++) { float dx = x[l] - mu; vs += dx*dx; }
#pragma unroll
    for (int off = 16; off; off >>= 1) vs += __shfl_xor_sync(0xffffffffu, vs, off);
    if (lane == 0) wred[wid] = vs;
    __syncthreads();
    float vtot = 0.f;
#pragma unroll
    for (int q = 0; q < 8; ++q) vtot += wred[q];
    float rstd = rsqrtf(vtot * (1.f/1024.f) + 1e-6f);

#pragma unroll
    for (int l = 0; l < 4; l++) {
        int c = tid + l*256;
        orow[c] = (x[l] - mu) * rstd * gamma[c] + beta[c];
    }
}

// ---------------- launch ----------------
extern "C" void kernel_launch(void* const* d_in, const int* in_sizes, int n_in,
                              void* d_out, int out_size)
{
    const float* w      = (const float*)d_in[0];
    const float* r      = (const float*)d_in[1];
    const float* mems   = (const float*)d_in[3];
    const float* qkvw   = (const float*)d_in[4];
    const float* rw     = (const float*)d_in[5];
    const float* ow     = (const float*)d_in[6];
    const float* rrb    = (const float*)d_in[7];
    const float* rwbias = (const float*)d_in[8];
    const float* gamma  = (const float*)d_in[9];
    const float* beta   = (const float*)d_in[10];
    float* out = (float*)d_out;

    __half *Ah, *Wth, *R2h, *RWth, *OWth, *AVh;
    cudaGetSymbolAddress((void**)&Ah,  g_Ah);
    cudaGetSymbolAddress((void**)&Wth, g_Wth);
    cudaGetSymbolAddress((void**)&R2h, g_R2h);
    cudaGetSymbolAddress((void**)&RWth,g_RWth);
    cudaGetSymbolAddress((void**)&OWth,g_OWth);
    cudaGetSymbolAddress((void**)&AVh, g_AVh);

    cudaFuncSetAttribute(gemm_hf<0>, cudaFuncAttributeMaxDynamicSharedMemorySize, GTC_SMEM);
    cudaFuncSetAttribute(gemm_hf<1>, cudaFuncAttributeMaxDynamicSharedMemorySize, GTC_SMEM);
    cudaFuncSetAttribute(gemm_hf<2>, cudaFuncAttributeMaxDynamicSharedMemorySize, GTC_SMEM);
    cudaFuncSetAttribute(bd_mma,   cudaFuncAttributeMaxDynamicSharedMemorySize, BD_SMEM);
    cudaFuncSetAttribute(attn_mma, cudaFuncAttributeMaxDynamicSharedMemorySize, ATT_SMEM);

    // prep
    round2_k<<<16384, 256>>>(mems, w, Ah, 2097152);
    tround_k<<<dim3(96, 32), 256>>>(qkvw, Wth, 1024, 3072);
    round_k <<<1024, 256>>>(r, R2h, 262144);
    tround_k<<<dim3(32, 32), 256>>>(rw, RWth, 1024, 1024);
    tround_k<<<dim3(32, 32), 256>>>(ow, OWth, 1024, 1024);

    // GEMMs (epilogues write attention operands directly)
    gemm_hf<0><<<dim3(24, 128), 256, GTC_SMEM>>>(Ah, Wth, nullptr, rwbias, rrb);
    gemm_hf<1><<<dim3(8, 8),    256, GTC_SMEM>>>(R2h, RWth, nullptr, nullptr, nullptr);
    vtrans_k<<<dim3(16, 256), 256>>>();

    // BD + attention (i-tile 128, heavy tiles first)
    bd_mma  <<<dim3(4, 256), 128, BD_SMEM>>>();
    attn_mma<<<dim3(4, 256), 128, ATT_SMEM>>>();

    // output projection + layernorm
    gemm_hf<2><<<dim3(8, 64),   256, GTC_SMEM>>>(AVh, OWth, out, nullptr, nullptr);
    ln_kernel  <<<8192, 256>>>(w, gamma, beta, out);
}